// round 12
// baseline (speedup 1.0000x reference)
#include <cuda_runtime.h>
#include <cuda_bf16.h>
#include <cstdint>

#define NN 2048
#define LL 512
#define KK 16
#define DIMV 1024

typedef unsigned int u32;
typedef __nv_bfloat16 bf16;

// ---------------- scratch (static device memory; no allocs allowed) ----------
__device__ float g_R [NN * NN];
__device__ float g_d [DIMV];
__device__ float g_part[16 * DIMV];
__device__ int   g_winv[NN];
__device__ int   g_colmap[NN];
__device__ bf16 g_Ah [NN * NN],    g_Al [NN * NN];
__device__ bf16 g_Wh [NN * NN],    g_Wl [NN * NN];
__device__ bf16 g_T1ah[DIMV * NN], g_T1al[DIMV * NN];
__device__ bf16 g_Dh [DIMV * DIMV], g_Dl [DIMV * DIMV];
__device__ bf16 g_FTh[NN * DIMV],  g_FTl[NN * DIMV];
__device__ bf16 g_WTh[NN * NN],    g_WTl[NN * NN];
__device__ bf16 g_Bph[NN * NN],    g_Bpl[NN * NN];

__device__ __forceinline__ u32 smem_u32(const void* p) {
    u32 a;
    asm("{ .reg .u64 t; cvta.to.shared.u64 t, %1; cvt.u32.u64 %0, t; }" : "=r"(a) : "l"(p));
    return a;
}

__device__ __forceinline__ u32 split2(float x, float y, u32& lo) {
    bf16 hx = __float2bfloat16(x), hy = __float2bfloat16(y);
    bf16 lx = __float2bfloat16(x - __bfloat162float(hx));
    bf16 ly = __float2bfloat16(y - __bfloat162float(hy));
    __nv_bfloat162 l2 = __halves2bfloat162(lx, ly);
    lo = *(u32*)&l2;
    __nv_bfloat162 h2 = __halves2bfloat162(hx, hy);
    return *(u32*)&h2;
}

// ---------------- right scan (R5 structure, MLP-batched inner dot) ------------
#define RWIN 8
__global__ void __launch_bounds__(256, 1) k_right(const float* __restrict__ Og,
                                                  const int* __restrict__ idxg) {
    extern __shared__ char smc[];
    float* Rt   = (float*)smc;                     // 8 slabs x NN x 2
    float* OsT  = Rt + 8 * NN * 2;                 // RWIN x 256 (transposed [k][i])
    int*   idsS = (int*)(OsT + RWIN * 256);        // RWIN x 16
    char*  tch  = (char*)(idsS + RWIN * 16);       // 8 x NN

    const int tid = threadIdx.x, lane = tid & 31, w = tid >> 5;
    const int c0 = blockIdx.x * KK;
    float* wr = Rt + w * (NN * 2);
    char*  wt = tch + w * NN;

    for (int r = lane; r < NN; r += 32) { wr[r * 2] = 0.f; wr[r * 2 + 1] = 0.f; wt[r] = 0; }
    __syncwarp();
    if (lane < 2) {
        int gc = c0 + w * 2 + lane;
        wr[gc * 2 + lane] = 1.0f;
        wt[gc] = 1;
    }

    const int i = lane >> 1, c = lane & 1;
    for (int w0 = 0; w0 < LL; w0 += RWIN) {
        __syncthreads();
#pragma unroll
        for (int s = 0; s < RWIN; s++) {
            int ii = tid >> 4, kk = tid & 15;
            OsT[s * 256 + kk * 16 + ii] = Og[(size_t)(w0 + s) * 256 + ii * 16 + kk];
        }
        if (tid < RWIN * 16) idsS[tid] = idxg[w0 * 16 + tid];
        __syncthreads();

        for (int s = 0; s < RWIN; s++) {
            const int* ids = idsS + s * 16;
            const float* Ot = OsT + s * 256;
            int myid = ids[lane & 15];
            bool hit = (lane < 16) && wt[myid];
            if (!__ballot_sync(0xffffffffu, hit)) continue;

            int idr[KK];
#pragma unroll
            for (int k = 0; k < KK; k++) idr[k] = ids[k];
            // batch ALL scattered reads first (MLP=16), then reduce
            float rv[KK];
#pragma unroll
            for (int k = 0; k < KK; k++) rv[k] = wr[idr[k] * 2 + c];
            float ov[KK];
#pragma unroll
            for (int k = 0; k < KK; k++) ov[k] = Ot[k * 16 + i];

            float y0 = 0.f, y1 = 0.f, y2 = 0.f, y3 = 0.f;
#pragma unroll
            for (int k = 0; k < KK; k += 4) {
                y0 += ov[k]     * rv[k];
                y1 += ov[k + 1] * rv[k + 1];
                y2 += ov[k + 2] * rv[k + 2];
                y3 += ov[k + 3] * rv[k + 3];
            }
            float y = (y0 + y1) + (y2 + y3);
            __syncwarp();
            int ri = idr[i];
            wr[ri * 2 + c] = y;
            if (c == 0) wt[ri] = 1;
            __syncwarp();
        }
    }
    __syncthreads();
    {
        int cc = tid & 15;
        const float* slab = Rt + (cc >> 1) * (NN * 2);
        int sc = cc & 1;
        for (int r = tid >> 4; r < NN; r += 16)
            g_R[(size_t)r * NN + c0 + cc] = slab[r * 2 + sc];
    }
}

// ---------------- mma.sync bf16x3 GEMM: C[m,n] = sum_k A[m,k]*B[n,k] ---------
// 128x128 tile, 256 threads (2x4 warps, 64x32 each), K-chunk 32, 3-stage cp.async.
// EPI bits: 1=fp32 C, 2=bf16 hi/lo C, 4=bf16 only rows>=1024, 8=rowdot rows<1024,
//           16=symmetric C (lower-triangle linear grid + mirror writes of all outputs).
#define PITCH 80
#define MATB  (128 * PITCH)
#define STAGE (4 * MATB)
#define SMG   (3 * STAGE + 2048)

__device__ __forceinline__ void mma_bf16(float* c, const u32* a, u32 b0, u32 b1) {
    asm volatile(
        "mma.sync.aligned.m16n8k16.row.col.f32.bf16.bf16.f32 "
        "{%0,%1,%2,%3}, {%4,%5,%6,%7}, {%8,%9}, {%0,%1,%2,%3};"
        : "+f"(c[0]), "+f"(c[1]), "+f"(c[2]), "+f"(c[3])
        : "r"(a[0]), "r"(a[1]), "r"(a[2]), "r"(a[3]), "r"(b0), "r"(b1));
}

template<int EPI>
__global__ __launch_bounds__(256, 1)
void k_mma(const bf16* __restrict__ Ah, const bf16* __restrict__ Al, int lda,
           const bf16* __restrict__ Bh, const bf16* __restrict__ Bl, int ldb,
           int K, float* __restrict__ Cf, int ldc,
           bf16* __restrict__ Ch, bf16* __restrict__ Cl, int ldch,
           const float* __restrict__ Wf, float* __restrict__ gpart) {
    extern __shared__ char sm[];
    const u32 sbase = smem_u32(sm);

    const int tid  = threadIdx.x;
    const int lane = tid & 31, warp = tid >> 5;
    const int wm = warp >> 2, wn = warp & 3;

    int bx, by;
    if (EPI & 16) {
        int t = blockIdx.x;
        by = (int)((sqrtf(8.0f * (float)t + 1.0f) - 1.0f) * 0.5f);
        while ((by + 1) * (by + 2) / 2 <= t) by++;
        while (by * (by + 1) / 2 > t) by--;
        bx = t - by * (by + 1) / 2;          // bx <= by
    } else {
        bx = blockIdx.x; by = blockIdx.y;
    }

    const int r0 = tid >> 2;
    const int sg = tid & 3;

    const bf16* gA[2] = { Ah, Al };
    const bf16* gB[2] = { Bh, Bl };

    auto issue_stage = [&](int buf, int kt) {
        u32 s = sbase + buf * STAGE;
#pragma unroll
        for (int h = 0; h < 2; h++) {
#pragma unroll
            for (int rr = 0; rr < 2; rr++) {
                int r = r0 + rr * 64;
                const void* srcA = gA[h] + (size_t)(by * 128 + r) * lda + kt + sg * 8;
                u32 dstA = s + h * MATB + r * PITCH + sg * 16;
                asm volatile("cp.async.cg.shared.global [%0], [%1], 16;"
                             :: "r"(dstA), "l"(srcA));
                const void* srcB = gB[h] + (size_t)(bx * 128 + r) * ldb + kt + sg * 8;
                u32 dstB = s + (2 + h) * MATB + r * PITCH + sg * 16;
                asm volatile("cp.async.cg.shared.global [%0], [%1], 16;"
                             :: "r"(dstB), "l"(srcB));
            }
        }
        asm volatile("cp.async.commit_group;" ::: "memory");
    };

    float acc[4][4][4];
#pragma unroll
    for (int mt = 0; mt < 4; mt++)
#pragma unroll
        for (int nt = 0; nt < 4; nt++)
#pragma unroll
            for (int j = 0; j < 4; j++) acc[mt][nt][j] = 0.0f;

    const int KT = K / 32;
    issue_stage(0, 0);
    issue_stage(1, 32);

    for (int c = 0; c < KT; c++) {
        if (c + 1 < KT) asm volatile("cp.async.wait_group 1;" ::: "memory");
        else            asm volatile("cp.async.wait_group 0;" ::: "memory");
        __syncthreads();
        if (c + 2 < KT) issue_stage((c + 2) % 3, (c + 2) * 32);
        const u32 s = sbase + (c % 3) * STAGE;

#pragma unroll
        for (int kh = 0; kh < 2; kh++) {
            const u32 lrow = (u32)(lane & 15) * PITCH + kh * 32 + (lane >> 4) * 16;
            u32 aF[2][4][4];
#pragma unroll
            for (int h = 0; h < 2; h++)
#pragma unroll
                for (int mt = 0; mt < 4; mt++) {
                    u32 ad = s + h * MATB + (u32)(wm * 64 + mt * 16) * PITCH + lrow;
                    asm volatile("ldmatrix.sync.aligned.m8n8.x4.shared.b16 "
                                 "{%0,%1,%2,%3}, [%4];"
                                 : "=r"(aF[h][mt][0]), "=r"(aF[h][mt][1]),
                                   "=r"(aF[h][mt][2]), "=r"(aF[h][mt][3]) : "r"(ad));
                }
            u32 bF[2][2][4];
#pragma unroll
            for (int h = 0; h < 2; h++)
#pragma unroll
                for (int np = 0; np < 2; np++) {
                    u32 ad = s + (2 + h) * MATB + (u32)(wn * 32 + np * 16) * PITCH + lrow;
                    asm volatile("ldmatrix.sync.aligned.m8n8.x4.shared.b16 "
                                 "{%0,%1,%2,%3}, [%4];"
                                 : "=r"(bF[h][np][0]), "=r"(bF[h][np][1]),
                                   "=r"(bF[h][np][2]), "=r"(bF[h][np][3]) : "r"(ad));
                }
#pragma unroll
            for (int mt = 0; mt < 4; mt++)
#pragma unroll
                for (int nt = 0; nt < 4; nt++) {
                    const int np = nt >> 1, sel = nt & 1;
                    u32 b0h = bF[0][np][sel], b1h = bF[0][np][sel + 2];
                    u32 b0l = bF[1][np][sel], b1l = bF[1][np][sel + 2];
                    mma_bf16(acc[mt][nt], aF[0][mt], b0h, b1h);
                    mma_bf16(acc[mt][nt], aF[0][mt], b0l, b1l);
                    mma_bf16(acc[mt][nt], aF[1][mt], b0h, b1h);
                }
        }
    }

    const int g = lane >> 2, tig = lane & 3;
    const bool dot = (EPI & 8) && (by < 8);

    if (!dot) {
#pragma unroll
        for (int mt = 0; mt < 4; mt++)
#pragma unroll
            for (int nt = 0; nt < 4; nt++)
#pragma unroll
                for (int hf = 0; hf < 2; hf++) {
                    int row = by * 128 + wm * 64 + mt * 16 + g + hf * 8;
                    int col = bx * 128 + wn * 32 + nt * 8 + tig * 2;
                    float v0 = acc[mt][nt][hf * 2], v1 = acc[mt][nt][hf * 2 + 1];
                    if (EPI & 1) {
                        float2* p = (float2*)(Cf + (size_t)row * ldc + col);
                        *p = make_float2(v0, v1);
                    }
                    if (EPI & 2) {
                        int br = row;
                        bool wv = true;
                        if (EPI & 4) { wv = (row >= DIMV); br = row - DIMV; }
                        if (wv) {
                            u32 lo, hi = split2(v0, v1, lo);
                            *(u32*)(Ch + (size_t)br * ldch + col) = hi;
                            *(u32*)(Cl + (size_t)br * ldch + col) = lo;
                        }
                    }
                }
        // mirror tile for symmetric output (all enabled output kinds)
        if ((EPI & 16) && bx != by) {
            float* ts = (float*)sm;                   // 128 x 129 floats (reuse pipeline smem)
            __syncthreads();
#pragma unroll
            for (int mt = 0; mt < 4; mt++)
#pragma unroll
                for (int nt = 0; nt < 4; nt++)
#pragma unroll
                    for (int hf = 0; hf < 2; hf++) {
                        int rl = wm * 64 + mt * 16 + g + hf * 8;
                        int cl = wn * 32 + nt * 8 + tig * 2;
                        ts[(cl) * 129 + rl]     = acc[mt][nt][hf * 2];
                        ts[(cl + 1) * 129 + rl] = acc[mt][nt][hf * 2 + 1];
                    }
            __syncthreads();
            for (int e = tid; e < 128 * 32; e += 256) {
                int i = e >> 5, jq = e & 31;
                const float* src = &ts[i * 129 + jq * 4];
                float4 v = make_float4(src[0], src[1], src[2], src[3]);
                if (EPI & 1)
                    *(float4*)(Cf + (size_t)(bx * 128 + i) * ldc + by * 128 + jq * 4) = v;
                if (EPI & 2) {
                    u32 lo0, lo1;
                    u32 hi0 = split2(v.x, v.y, lo0);
                    u32 hi1 = split2(v.z, v.w, lo1);
                    *(uint2*)(Ch + (size_t)(bx * 128 + i) * ldch + by * 128 + jq * 4)
                        = make_uint2(hi0, hi1);
                    *(uint2*)(Cl + (size_t)(bx * 128 + i) * ldch + by * 128 + jq * 4)
                        = make_uint2(lo0, lo1);
                }
            }
        }
    } else {
        float rp[8];
#pragma unroll
        for (int q = 0; q < 8; q++) rp[q] = 0.f;
#pragma unroll
        for (int mt = 0; mt < 4; mt++)
#pragma unroll
            for (int hf = 0; hf < 2; hf++) {
                int row = by * 128 + wm * 64 + mt * 16 + g + hf * 8;
                const float* wrow = Wf + (size_t)row * NN;
#pragma unroll
                for (int nt = 0; nt < 4; nt++) {
                    int col = bx * 128 + wn * 32 + nt * 8 + tig * 2;
                    float2 wv = *(const float2*)(wrow + col);
                    rp[mt * 2 + hf] += acc[mt][nt][hf * 2] * wv.x
                                     + acc[mt][nt][hf * 2 + 1] * wv.y;
                }
            }
#pragma unroll
        for (int o = 1; o <= 2; o <<= 1)
#pragma unroll
            for (int q = 0; q < 8; q++)
                rp[q] += __shfl_xor_sync(0xffffffffu, rp[q], o);
        float* sred = (float*)(sm + 3 * STAGE);
        __syncthreads();
        if (tig == 0) {
#pragma unroll
            for (int mt = 0; mt < 4; mt++)
#pragma unroll
                for (int hf = 0; hf < 2; hf++) {
                    int rl = wm * 64 + mt * 16 + hf * 8 + g;
                    sred[rl * 4 + wn] = rp[mt * 2 + hf];
                }
        }
        __syncthreads();
        if (tid < 128) {
            float s2 = sred[tid * 4] + sred[tid * 4 + 1] + sred[tid * 4 + 2] + sred[tid * 4 + 3];
            gpart[bx * DIMV + by * 128 + tid] = s2;
        }
    }
}

// ---------------- fused prep: R row -> right, W fp32 (perm), Wh, Wl ----------
__global__ void __launch_bounds__(256) k_prep(const float* __restrict__ R,
                                              const int* __restrict__ winv,
                                              float* __restrict__ o_right,
                                              float* __restrict__ Wf,
                                              bf16* __restrict__ Wh,
                                              bf16* __restrict__ Wl) {
    int r = blockIdx.x, t = threadIdx.x;
    int p = winv[r];
    const float4* src = (const float4*)(R + (size_t)r * NN);
    float4* dr = (float4*)(o_right + (size_t)r * NN);
    float4* dw = (float4*)(Wf + (size_t)p * NN);
    uint2*  dh = (uint2*)(Wh + (size_t)p * NN);
    uint2*  dl = (uint2*)(Wl + (size_t)p * NN);
#pragma unroll
    for (int j = 0; j < 2; j++) {
        int k = t + j * 256;
        float4 v = src[k];
        dr[k] = v;
        dw[k] = v;
        u32 lo0, lo1;
        u32 hi0 = split2(v.x, v.y, lo0);
        u32 hi1 = split2(v.z, v.w, lo1);
        dh[k] = make_uint2(hi0, hi1);
        dl[k] = make_uint2(lo0, lo1);
    }
}

// ---------------- conv A -> bf16 hi/lo (8 elems/thread) -----------------------
__global__ void k_conv(const float* __restrict__ in, bf16* __restrict__ oh,
                       bf16* __restrict__ ol, int n8) {
    int t = blockIdx.x * 256 + threadIdx.x;
    if (t >= n8) return;
    float4 a = ((const float4*)in)[2 * t], b = ((const float4*)in)[2 * t + 1];
    u32 l0, l1, l2, l3;
    u32 h0 = split2(a.x, a.y, l0);
    u32 h1 = split2(a.z, a.w, l1);
    u32 h2 = split2(b.x, b.y, l2);
    u32 h3 = split2(b.z, b.w, l3);
    ((uint4*)oh)[t] = make_uint4(h0, h1, h2, h3);
    ((uint4*)ol)[t] = make_uint4(l0, l1, l2, l3);
}

// ---------------- bf16 hi/lo pair transpose: out[m][k] = in[k][m] -------------
__global__ void k_tbf(const bf16* __restrict__ ih, const bf16* __restrict__ il, int ldin,
                      bf16* __restrict__ oh, bf16* __restrict__ ol, int ldout) {
    __shared__ u32 th[64][33], tl[64][33];
    int k0 = blockIdx.x * 64, m0 = blockIdx.y * 64;
    int t = threadIdx.x;
#pragma unroll
    for (int j = 0; j < 8; j++) {
        int idx = t + j * 256;
        int kr = idx >> 5, mu = idx & 31;
        th[kr][mu] = *(const u32*)&ih[(size_t)(k0 + kr) * ldin + m0 + 2 * mu];
        tl[kr][mu] = *(const u32*)&il[(size_t)(k0 + kr) * ldin + m0 + 2 * mu];
    }
    __syncthreads();
#pragma unroll
    for (int j = 0; j < 8; j++) {
        int idx = t + j * 256;
        int mr = idx >> 5, ku = idx & 31;
        u32 u0 = th[2 * ku][mr >> 1], u1 = th[2 * ku + 1][mr >> 1];
        u32 v0 = tl[2 * ku][mr >> 1], v1 = tl[2 * ku + 1][mr >> 1];
        u32 sel = (mr & 1) ? 0x7632 : 0x5410;
        *(u32*)&oh[(size_t)(m0 + mr) * ldout + k0 + 2 * ku] = __byte_perm(u0, u1, sel);
        *(u32*)&ol[(size_t)(m0 + mr) * ldout + k0 + 2 * ku] = __byte_perm(v0, v1, sel);
    }
}

// ---------------- Bp left: Bp[n][k] = d[k] * R[inact[k]][n], bf16 split -------
__global__ void k_bpl(const float* __restrict__ R, const int* __restrict__ inact,
                      const float* __restrict__ dvec,
                      bf16* __restrict__ oh, bf16* __restrict__ ol) {
    __shared__ float tf[32][65];
    int k0 = blockIdx.x * 32, n0 = blockIdx.y * 64;
    int t = threadIdx.x;
#pragma unroll
    for (int j = 0; j < 8; j++) {
        int idx = t + j * 256;
        int kr = idx >> 6, nc = idx & 63;
        tf[kr][nc] = dvec[k0 + kr] * R[(size_t)inact[k0 + kr] * NN + n0 + nc];
    }
    __syncthreads();
#pragma unroll
    for (int j = 0; j < 4; j++) {
        int idx = t + j * 256;
        int nr = idx >> 4, ku = idx & 15;
        float v0 = tf[2 * ku][nr], v1 = tf[2 * ku + 1][nr];
        u32 lo, hi = split2(v0, v1, lo);
        *(u32*)&oh[(size_t)(n0 + nr) * NN + k0 + 2 * ku] = hi;
        *(u32*)&ol[(size_t)(n0 + nr) * NN + k0 + 2 * ku] = lo;
    }
}

// ---------------- maps / reductions / outputs ---------------------------------
__global__ void k_maps0(int* colmap) {
    int t = blockIdx.x * 256 + threadIdx.x;
    colmap[t] = -1;
}
__global__ void k_maps1(const int* __restrict__ act, const int* __restrict__ inact,
                        int* winv, int* colmap) {
    int t = blockIdx.x * 256 + threadIdx.x;
    winv[inact[t]] = t;
    winv[act[t]]   = DIMV + t;
    colmap[act[t]] = t;
}

__global__ void k_dred(const float* __restrict__ gpart, float* __restrict__ dvec) {
    int j = blockIdx.x * 256 + threadIdx.x;
    float s = 0.f;
#pragma unroll
    for (int b = 0; b < 16; b++) s += gpart[b * DIMV + j];
    dvec[j] = s;
}

// grid NN + DIMV: blocks < NN fill D rows; blocks >= NN fill mc rows.
__global__ void __launch_bounds__(256) k_dfill(const float* __restrict__ Daa,
                                               const int* __restrict__ colmap,
                                               const int* __restrict__ winv,
                                               const float* __restrict__ dvec,
                                               float* __restrict__ D,
                                               float* __restrict__ mc) {
    int gr = blockIdx.x, t = threadIdx.x;
    if (gr >= NN) {
        int j = gr - NN;
        float* row = mc + (size_t)j * DIMV;
        ((float4*)row)[t] = make_float4(0.f, 0.f, 0.f, 0.f);
        __syncthreads();
        if (t == 0) row[j] = dvec[j];
        return;
    }
    int a = colmap[gr];
    float* row = D + (size_t)gr * NN;
    if (a < 0) {
        float4 z = make_float4(0.f, 0.f, 0.f, 0.f);
#pragma unroll
        for (int j = 0; j < 2; j++) ((float4*)row)[t + j * 256] = z;
        __syncthreads();
        if (t == 0) row[gr] = dvec[winv[gr]];
    } else {
        const float* dr = Daa + (size_t)a * DIMV;
#pragma unroll
        for (int j = 0; j < 8; j++) {
            int cc = t + j * 256;
            int cm = colmap[cc];
            row[cc] = (cm >= 0) ? dr[cm] : 0.f;
        }
    }
}

// ---------------- launch ------------------------------------------------------
extern "C" void kernel_launch(void* const* d_in, const int* in_sizes, int n_in,
                              void* d_out, int out_size) {
    const float* A    = (const float*)d_in[0];
    const float* O    = (const float*)d_in[1];
    const int*   idx  = (const int*)d_in[2];
    const int*   act  = (const int*)d_in[3];
    const int*   inact= (const int*)d_in[4];
    float* out = (float*)d_out;

    float *R, *dv, *gpart;
    int *winv, *colmap;
    bf16 *Ah, *Al, *Wh, *Wl, *T1ah, *T1al, *Dh, *Dl, *FTh, *FTl, *WTh, *WTl, *Bph, *Bpl;
    cudaGetSymbolAddress((void**)&R,     g_R);
    cudaGetSymbolAddress((void**)&dv,    g_d);
    cudaGetSymbolAddress((void**)&gpart, g_part);
    cudaGetSymbolAddress((void**)&winv,  g_winv);
    cudaGetSymbolAddress((void**)&colmap,g_colmap);
    cudaGetSymbolAddress((void**)&Ah,  g_Ah);   cudaGetSymbolAddress((void**)&Al,  g_Al);
    cudaGetSymbolAddress((void**)&Wh,  g_Wh);   cudaGetSymbolAddress((void**)&Wl,  g_Wl);
    cudaGetSymbolAddress((void**)&T1ah,g_T1ah); cudaGetSymbolAddress((void**)&T1al,g_T1al);
    cudaGetSymbolAddress((void**)&Dh,  g_Dh);   cudaGetSymbolAddress((void**)&Dl,  g_Dl);
    cudaGetSymbolAddress((void**)&FTh, g_FTh);  cudaGetSymbolAddress((void**)&FTl, g_FTl);
    cudaGetSymbolAddress((void**)&WTh, g_WTh);  cudaGetSymbolAddress((void**)&WTl, g_WTl);
    cudaGetSymbolAddress((void**)&Bph, g_Bph);  cudaGetSymbolAddress((void**)&Bpl, g_Bpl);

    const size_t NN2 = (size_t)NN * NN;
    float* o_arec  = out;
    float* o_right = out + NN2;
    float* o_D     = out + 2 * NN2;
    float* o_mc    = out + 3 * NN2;
    float* o_fc    = o_mc + (size_t)DIMV * DIMV;
    float* o_mw    = o_fc + (size_t)DIMV * DIMV;   // W fp32 = [Mi;Fa] contiguous

    const int smemR = 8 * NN * 2 * 4 + RWIN * 256 * 4 + RWIN * 16 * 4 + 8 * NN;
    cudaFuncSetAttribute(k_right, cudaFuncAttributeMaxDynamicSharedMemorySize, smemR);
    cudaFuncSetAttribute(k_mma<14>, cudaFuncAttributeMaxDynamicSharedMemorySize, SMG);
    cudaFuncSetAttribute(k_mma<19>, cudaFuncAttributeMaxDynamicSharedMemorySize, SMG);
    cudaFuncSetAttribute(k_mma<2>,  cudaFuncAttributeMaxDynamicSharedMemorySize, SMG);
    cudaFuncSetAttribute(k_mma<17>, cudaFuncAttributeMaxDynamicSharedMemorySize, SMG);

    // 1. maps + A split
    k_maps0<<<NN / 256, 256>>>(colmap);
    k_maps1<<<DIMV / 256, 256>>>(act, inact, winv, colmap);
    k_conv<<<(int)(NN2 / 8 / 256), 256>>>(A, Ah, Al, (int)(NN2 / 8));

    // 2. right scan + fused prep
    k_right<<<NN / KK, 256, smemR>>>(O, idx);
    k_prep<<<NN, 256>>>(R, winv, o_right, o_mw, Wh, Wl);

    // 3. T1 = W @ A (A sym, NT). rows<1024: fused rowdot; rows>=1024: bf16 T1a
    k_mma<14><<<dim3(16, 16), 256, SMG>>>(Wh, Wl, NN, Ah, Al, NN, NN,
                                          nullptr, 0, T1ah, T1al, NN, o_mw, gpart);
    k_dred<<<DIMV / 256, 256>>>(gpart, dv);

    // 4. father_coefficients = D_aa = T1a @ Fa^T — symmetric: 36 triangle tiles,
    //    mirror fp32 (o_fc) + bf16 (Dh/Dl)
    k_mma<19><<<36, 256, SMG>>>(T1ah, T1al, NN,
                                Wh + (size_t)DIMV * NN, Wl + (size_t)DIMV * NN, NN,
                                NN, o_fc, DIMV, Dh, Dl, DIMV, nullptr, nullptr);

    // 5. FaT = Fa^T
    k_tbf<<<dim3(DIMV / 64, NN / 64), 256>>>(Wh + (size_t)DIMV * NN, Wl + (size_t)DIMV * NN,
                                             NN, FTh, FTl, DIMV);

    // 6. P = FaT @ D_aa (D_aa sym) -> B' right half
    k_mma<2><<<dim3(8, 16), 256, SMG>>>(FTh, FTl, DIMV, Dh, Dl, DIMV, DIMV,
                                        nullptr, 0, Bph + DIMV, Bpl + DIMV, NN,
                                        nullptr, nullptr);

    // 7. B' left half: d[k] * Mi[k][n]
    k_bpl<<<dim3(DIMV / 32, NN / 64), 256>>>(R, inact, dv, Bph, Bpl);

    // 8. WT = W^T
    k_tbf<<<dim3(NN / 64, NN / 64), 256>>>(Wh, Wl, NN, WTh, WTl, NN);

    // 9. A_rec = WT @ B'^T (symmetric: 136 lower-triangle tiles + mirror)
    k_mma<17><<<136, 256, SMG>>>(WTh, WTl, NN, Bph, Bpl, NN, NN,
                                 o_arec, NN, nullptr, nullptr, 0,
                                 nullptr, nullptr);

    // 10. D + mother_coefficients (one kernel)
    k_dfill<<<NN + DIMV, 256>>>(o_fc, colmap, winv, dv, o_D, o_mc);
}

// round 13
// speedup vs baseline: 1.0589x; 1.0589x over previous
#include <cuda_runtime.h>
#include <cuda_bf16.h>
#include <cstdint>

#define NN 2048
#define LL 512
#define KK 16
#define DIMV 1024

typedef unsigned int u32;
typedef __nv_bfloat16 bf16;

// ---------------- scratch (static device memory; no allocs allowed) ----------
__device__ float g_R [NN * NN];
__device__ float g_d [DIMV];
__device__ float g_part[16 * DIMV];
__device__ int   g_winv[NN];
__device__ int   g_colmap[NN];
__device__ bf16 g_Ah [NN * NN],    g_Al [NN * NN];
__device__ bf16 g_Wh [NN * NN],    g_Wl [NN * NN];
__device__ bf16 g_T1ah[DIMV * NN], g_T1al[DIMV * NN];
__device__ bf16 g_Dh [DIMV * DIMV], g_Dl [DIMV * DIMV];
__device__ bf16 g_FTh[NN * DIMV],  g_FTl[NN * DIMV];
__device__ bf16 g_WTh[NN * NN],    g_WTl[NN * NN];
__device__ bf16 g_Bph[NN * NN],    g_Bpl[NN * NN];

__device__ __forceinline__ u32 smem_u32(const void* p) {
    u32 a;
    asm("{ .reg .u64 t; cvta.to.shared.u64 t, %1; cvt.u32.u64 %0, t; }" : "=r"(a) : "l"(p));
    return a;
}

__device__ __forceinline__ u32 split2(float x, float y, u32& lo) {
    bf16 hx = __float2bfloat16(x), hy = __float2bfloat16(y);
    bf16 lx = __float2bfloat16(x - __bfloat162float(hx));
    bf16 ly = __float2bfloat16(y - __bfloat162float(hy));
    __nv_bfloat162 l2 = __halves2bfloat162(lx, ly);
    lo = *(u32*)&l2;
    __nv_bfloat162 h2 = __halves2bfloat162(hx, hy);
    return *(u32*)&h2;
}

// ---------------- right scan (R5 structure, batch-8 MLP dot, reg-bounded) -----
#define RWIN 8
__global__ void __launch_bounds__(256) k_right(const float* __restrict__ Og,
                                               const int* __restrict__ idxg) {
    extern __shared__ char smc[];
    float* Rt   = (float*)smc;                     // 8 slabs x NN x 2
    float* OsT  = Rt + 8 * NN * 2;                 // RWIN x 256 (transposed [k][i])
    int*   idsS = (int*)(OsT + RWIN * 256);        // RWIN x 16
    char*  tch  = (char*)(idsS + RWIN * 16);       // 8 x NN

    const int tid = threadIdx.x, lane = tid & 31, w = tid >> 5;
    const int c0 = blockIdx.x * KK;
    float* wr = Rt + w * (NN * 2);
    char*  wt = tch + w * NN;

    for (int r = lane; r < NN; r += 32) { wr[r * 2] = 0.f; wr[r * 2 + 1] = 0.f; wt[r] = 0; }
    __syncwarp();
    if (lane < 2) {
        int gc = c0 + w * 2 + lane;
        wr[gc * 2 + lane] = 1.0f;
        wt[gc] = 1;
    }

    const int i = lane >> 1, c = lane & 1;
    for (int w0 = 0; w0 < LL; w0 += RWIN) {
        __syncthreads();
#pragma unroll
        for (int s = 0; s < RWIN; s++) {
            int ii = tid >> 4, kk = tid & 15;
            OsT[s * 256 + kk * 16 + ii] = Og[(size_t)(w0 + s) * 256 + ii * 16 + kk];
        }
        if (tid < RWIN * 16) idsS[tid] = idxg[w0 * 16 + tid];
        __syncthreads();

        for (int s = 0; s < RWIN; s++) {
            const int* ids = idsS + s * 16;
            const float* Ot = OsT + s * 256;
            int myid = ids[lane & 15];
            bool hit = (lane < 16) && wt[myid];
            if (!__ballot_sync(0xffffffffu, hit)) continue;

            // batch 8 scattered reads, reduce, then the next 8 (bounded regs)
            float rv0[8];
#pragma unroll
            for (int k = 0; k < 8; k++) rv0[k] = wr[ids[k] * 2 + c];
            float y0 = 0.f;
#pragma unroll
            for (int k = 0; k < 8; k++) y0 += Ot[k * 16 + i] * rv0[k];
            float rv1[8];
#pragma unroll
            for (int k = 0; k < 8; k++) rv1[k] = wr[ids[8 + k] * 2 + c];
            float y1 = 0.f;
#pragma unroll
            for (int k = 0; k < 8; k++) y1 += Ot[(8 + k) * 16 + i] * rv1[k];
            float y = y0 + y1;
            __syncwarp();
            int ri = ids[i];
            wr[ri * 2 + c] = y;
            if (c == 0) wt[ri] = 1;
            __syncwarp();
        }
    }
    __syncthreads();
    {
        int cc = tid & 15;
        const float* slab = Rt + (cc >> 1) * (NN * 2);
        int sc = cc & 1;
        for (int r = tid >> 4; r < NN; r += 16)
            g_R[(size_t)r * NN + c0 + cc] = slab[r * 2 + sc];
    }
}

// ---------------- mma.sync bf16x3 GEMM: C[m,n] = sum_k A[m,k]*B[n,k] ---------
// 128x128 tile, 256 threads (2x4 warps, 64x32 each), K-chunk 32, 3-stage cp.async.
// EPI bits: 1=fp32 C, 2=bf16 hi/lo C, 4=bf16 only rows>=1024, 8=rowdot rows<1024,
//           16=symmetric C (lower-triangle linear grid + mirror writes).
#define PITCH 80
#define MATB  (128 * PITCH)
#define STAGE (4 * MATB)
#define SMG   (3 * STAGE + 2048)

__device__ __forceinline__ void mma_bf16(float* c, const u32* a, u32 b0, u32 b1) {
    asm volatile(
        "mma.sync.aligned.m16n8k16.row.col.f32.bf16.bf16.f32 "
        "{%0,%1,%2,%3}, {%4,%5,%6,%7}, {%8,%9}, {%0,%1,%2,%3};"
        : "+f"(c[0]), "+f"(c[1]), "+f"(c[2]), "+f"(c[3])
        : "r"(a[0]), "r"(a[1]), "r"(a[2]), "r"(a[3]), "r"(b0), "r"(b1));
}

template<int EPI>
__global__ __launch_bounds__(256, 1)
void k_mma(const bf16* __restrict__ Ah, const bf16* __restrict__ Al, int lda,
           const bf16* __restrict__ Bh, const bf16* __restrict__ Bl, int ldb,
           int K, float* __restrict__ Cf, int ldc,
           bf16* __restrict__ Ch, bf16* __restrict__ Cl, int ldch,
           const float* __restrict__ Wf, float* __restrict__ gpart) {
    extern __shared__ char sm[];
    const u32 sbase = smem_u32(sm);

    const int tid  = threadIdx.x;
    const int lane = tid & 31, warp = tid >> 5;
    const int wm = warp >> 2, wn = warp & 3;

    int bx, by;
    if (EPI & 16) {
        int t = blockIdx.x;
        by = (int)((sqrtf(8.0f * (float)t + 1.0f) - 1.0f) * 0.5f);
        while ((by + 1) * (by + 2) / 2 <= t) by++;
        while (by * (by + 1) / 2 > t) by--;
        bx = t - by * (by + 1) / 2;          // bx <= by
    } else {
        bx = blockIdx.x; by = blockIdx.y;
    }

    const int r0 = tid >> 2;
    const int sg = tid & 3;

    const bf16* gA[2] = { Ah, Al };
    const bf16* gB[2] = { Bh, Bl };

    auto issue_stage = [&](int buf, int kt) {
        u32 s = sbase + buf * STAGE;
#pragma unroll
        for (int h = 0; h < 2; h++) {
#pragma unroll
            for (int rr = 0; rr < 2; rr++) {
                int r = r0 + rr * 64;
                const void* srcA = gA[h] + (size_t)(by * 128 + r) * lda + kt + sg * 8;
                u32 dstA = s + h * MATB + r * PITCH + sg * 16;
                asm volatile("cp.async.cg.shared.global [%0], [%1], 16;"
                             :: "r"(dstA), "l"(srcA));
                const void* srcB = gB[h] + (size_t)(bx * 128 + r) * ldb + kt + sg * 8;
                u32 dstB = s + (2 + h) * MATB + r * PITCH + sg * 16;
                asm volatile("cp.async.cg.shared.global [%0], [%1], 16;"
                             :: "r"(dstB), "l"(srcB));
            }
        }
        asm volatile("cp.async.commit_group;" ::: "memory");
    };

    float acc[4][4][4];
#pragma unroll
    for (int mt = 0; mt < 4; mt++)
#pragma unroll
        for (int nt = 0; nt < 4; nt++)
#pragma unroll
            for (int j = 0; j < 4; j++) acc[mt][nt][j] = 0.0f;

    const int KT = K / 32;
    issue_stage(0, 0);
    issue_stage(1, 32);

    for (int c = 0; c < KT; c++) {
        if (c + 1 < KT) asm volatile("cp.async.wait_group 1;" ::: "memory");
        else            asm volatile("cp.async.wait_group 0;" ::: "memory");
        __syncthreads();
        if (c + 2 < KT) issue_stage((c + 2) % 3, (c + 2) * 32);
        const u32 s = sbase + (c % 3) * STAGE;

#pragma unroll
        for (int kh = 0; kh < 2; kh++) {
            const u32 lrow = (u32)(lane & 15) * PITCH + kh * 32 + (lane >> 4) * 16;
            u32 aF[2][4][4];
#pragma unroll
            for (int h = 0; h < 2; h++)
#pragma unroll
                for (int mt = 0; mt < 4; mt++) {
                    u32 ad = s + h * MATB + (u32)(wm * 64 + mt * 16) * PITCH + lrow;
                    asm volatile("ldmatrix.sync.aligned.m8n8.x4.shared.b16 "
                                 "{%0,%1,%2,%3}, [%4];"
                                 : "=r"(aF[h][mt][0]), "=r"(aF[h][mt][1]),
                                   "=r"(aF[h][mt][2]), "=r"(aF[h][mt][3]) : "r"(ad));
                }
            u32 bF[2][2][4];
#pragma unroll
            for (int h = 0; h < 2; h++)
#pragma unroll
                for (int np = 0; np < 2; np++) {
                    u32 ad = s + (2 + h) * MATB + (u32)(wn * 32 + np * 16) * PITCH + lrow;
                    asm volatile("ldmatrix.sync.aligned.m8n8.x4.shared.b16 "
                                 "{%0,%1,%2,%3}, [%4];"
                                 : "=r"(bF[h][np][0]), "=r"(bF[h][np][1]),
                                   "=r"(bF[h][np][2]), "=r"(bF[h][np][3]) : "r"(ad));
                }
#pragma unroll
            for (int mt = 0; mt < 4; mt++)
#pragma unroll
                for (int nt = 0; nt < 4; nt++) {
                    const int np = nt >> 1, sel = nt & 1;
                    u32 b0h = bF[0][np][sel], b1h = bF[0][np][sel + 2];
                    u32 b0l = bF[1][np][sel], b1l = bF[1][np][sel + 2];
                    mma_bf16(acc[mt][nt], aF[0][mt], b0h, b1h);
                    mma_bf16(acc[mt][nt], aF[0][mt], b0l, b1l);
                    mma_bf16(acc[mt][nt], aF[1][mt], b0h, b1h);
                }
        }
    }

    const int g = lane >> 2, tig = lane & 3;
    const bool dot = (EPI & 8) && (by < 8);

    if (!dot) {
#pragma unroll
        for (int mt = 0; mt < 4; mt++)
#pragma unroll
            for (int nt = 0; nt < 4; nt++)
#pragma unroll
                for (int hf = 0; hf < 2; hf++) {
                    int row = by * 128 + wm * 64 + mt * 16 + g + hf * 8;
                    int col = bx * 128 + wn * 32 + nt * 8 + tig * 2;
                    float v0 = acc[mt][nt][hf * 2], v1 = acc[mt][nt][hf * 2 + 1];
                    if (EPI & 1) {
                        float2* p = (float2*)(Cf + (size_t)row * ldc + col);
                        *p = make_float2(v0, v1);
                    }
                    if (EPI & 2) {
                        int br = row;
                        bool wv = true;
                        if (EPI & 4) { wv = (row >= DIMV); br = row - DIMV; }
                        if (wv) {
                            u32 lo, hi = split2(v0, v1, lo);
                            *(u32*)(Ch + (size_t)br * ldch + col) = hi;
                            *(u32*)(Cl + (size_t)br * ldch + col) = lo;
                        }
                    }
                }
        // mirror tile for symmetric output
        if ((EPI & 16) && bx != by) {
            float* ts = (float*)sm;                   // 128 x 129 floats
            __syncthreads();
#pragma unroll
            for (int mt = 0; mt < 4; mt++)
#pragma unroll
                for (int nt = 0; nt < 4; nt++)
#pragma unroll
                    for (int hf = 0; hf < 2; hf++) {
                        int rl = wm * 64 + mt * 16 + g + hf * 8;
                        int cl = wn * 32 + nt * 8 + tig * 2;
                        ts[(cl) * 129 + rl]     = acc[mt][nt][hf * 2];
                        ts[(cl + 1) * 129 + rl] = acc[mt][nt][hf * 2 + 1];
                    }
            __syncthreads();
            for (int e = tid; e < 128 * 32; e += 256) {
                int i = e >> 5, jq = e & 31;
                const float* src = &ts[i * 129 + jq * 4];
                float4 v = make_float4(src[0], src[1], src[2], src[3]);
                if (EPI & 1)
                    *(float4*)(Cf + (size_t)(bx * 128 + i) * ldc + by * 128 + jq * 4) = v;
                if (EPI & 2) {
                    u32 lo0, lo1;
                    u32 hi0 = split2(v.x, v.y, lo0);
                    u32 hi1 = split2(v.z, v.w, lo1);
                    *(uint2*)(Ch + (size_t)(bx * 128 + i) * ldch + by * 128 + jq * 4)
                        = make_uint2(hi0, hi1);
                    *(uint2*)(Cl + (size_t)(bx * 128 + i) * ldch + by * 128 + jq * 4)
                        = make_uint2(lo0, lo1);
                }
            }
        }
    } else {
        float rp[8];
#pragma unroll
        for (int q = 0; q < 8; q++) rp[q] = 0.f;
#pragma unroll
        for (int mt = 0; mt < 4; mt++)
#pragma unroll
            for (int hf = 0; hf < 2; hf++) {
                int row = by * 128 + wm * 64 + mt * 16 + g + hf * 8;
                const float* wrow = Wf + (size_t)row * NN;
#pragma unroll
                for (int nt = 0; nt < 4; nt++) {
                    int col = bx * 128 + wn * 32 + nt * 8 + tig * 2;
                    float2 wv = *(const float2*)(wrow + col);
                    rp[mt * 2 + hf] += acc[mt][nt][hf * 2] * wv.x
                                     + acc[mt][nt][hf * 2 + 1] * wv.y;
                }
            }
#pragma unroll
        for (int o = 1; o <= 2; o <<= 1)
#pragma unroll
            for (int q = 0; q < 8; q++)
                rp[q] += __shfl_xor_sync(0xffffffffu, rp[q], o);
        float* sred = (float*)(sm + 3 * STAGE);
        __syncthreads();
        if (tig == 0) {
#pragma unroll
            for (int mt = 0; mt < 4; mt++)
#pragma unroll
                for (int hf = 0; hf < 2; hf++) {
                    int rl = wm * 64 + mt * 16 + hf * 8 + g;
                    sred[rl * 4 + wn] = rp[mt * 2 + hf];
                }
        }
        __syncthreads();
        if (tid < 128) {
            float s2 = sred[tid * 4] + sred[tid * 4 + 1] + sred[tid * 4 + 2] + sred[tid * 4 + 3];
            gpart[bx * DIMV + by * 128 + tid] = s2;
        }
    }
}

// ---------------- fused prep: R row -> right, W fp32 (perm), Wh, Wl ----------
__global__ void __launch_bounds__(256) k_prep(const float* __restrict__ R,
                                              const int* __restrict__ winv,
                                              float* __restrict__ o_right,
                                              float* __restrict__ Wf,
                                              bf16* __restrict__ Wh,
                                              bf16* __restrict__ Wl) {
    int r = blockIdx.x, t = threadIdx.x;
    int p = winv[r];
    const float4* src = (const float4*)(R + (size_t)r * NN);
    float4* dr = (float4*)(o_right + (size_t)r * NN);
    float4* dw = (float4*)(Wf + (size_t)p * NN);
    uint2*  dh = (uint2*)(Wh + (size_t)p * NN);
    uint2*  dl = (uint2*)(Wl + (size_t)p * NN);
#pragma unroll
    for (int j = 0; j < 2; j++) {
        int k = t + j * 256;
        float4 v = src[k];
        dr[k] = v;
        dw[k] = v;
        u32 lo0, lo1;
        u32 hi0 = split2(v.x, v.y, lo0);
        u32 hi1 = split2(v.z, v.w, lo1);
        dh[k] = make_uint2(hi0, hi1);
        dl[k] = make_uint2(lo0, lo1);
    }
}

// ---------------- conv A -> bf16 hi/lo (8 elems/thread) -----------------------
__global__ void k_conv(const float* __restrict__ in, bf16* __restrict__ oh,
                       bf16* __restrict__ ol, int n8) {
    int t = blockIdx.x * 256 + threadIdx.x;
    if (t >= n8) return;
    float4 a = ((const float4*)in)[2 * t], b = ((const float4*)in)[2 * t + 1];
    u32 l0, l1, l2, l3;
    u32 h0 = split2(a.x, a.y, l0);
    u32 h1 = split2(a.z, a.w, l1);
    u32 h2 = split2(b.x, b.y, l2);
    u32 h3 = split2(b.z, b.w, l3);
    ((uint4*)oh)[t] = make_uint4(h0, h1, h2, h3);
    ((uint4*)ol)[t] = make_uint4(l0, l1, l2, l3);
}

// ---------------- bf16 hi/lo pair transpose: out[m][k] = in[k][m] -------------
__global__ void k_tbf(const bf16* __restrict__ ih, const bf16* __restrict__ il, int ldin,
                      bf16* __restrict__ oh, bf16* __restrict__ ol, int ldout) {
    __shared__ u32 th[64][33], tl[64][33];
    int k0 = blockIdx.x * 64, m0 = blockIdx.y * 64;
    int t = threadIdx.x;
#pragma unroll
    for (int j = 0; j < 8; j++) {
        int idx = t + j * 256;
        int kr = idx >> 5, mu = idx & 31;
        th[kr][mu] = *(const u32*)&ih[(size_t)(k0 + kr) * ldin + m0 + 2 * mu];
        tl[kr][mu] = *(const u32*)&il[(size_t)(k0 + kr) * ldin + m0 + 2 * mu];
    }
    __syncthreads();
#pragma unroll
    for (int j = 0; j < 8; j++) {
        int idx = t + j * 256;
        int mr = idx >> 5, ku = idx & 31;
        u32 u0 = th[2 * ku][mr >> 1], u1 = th[2 * ku + 1][mr >> 1];
        u32 v0 = tl[2 * ku][mr >> 1], v1 = tl[2 * ku + 1][mr >> 1];
        u32 sel = (mr & 1) ? 0x7632 : 0x5410;
        *(u32*)&oh[(size_t)(m0 + mr) * ldout + k0 + 2 * ku] = __byte_perm(u0, u1, sel);
        *(u32*)&ol[(size_t)(m0 + mr) * ldout + k0 + 2 * ku] = __byte_perm(v0, v1, sel);
    }
}

// ---------------- Bp left: Bp[n][k] = d[k] * R[inact[k]][n], bf16 split -------
__global__ void k_bpl(const float* __restrict__ R, const int* __restrict__ inact,
                      const float* __restrict__ dvec,
                      bf16* __restrict__ oh, bf16* __restrict__ ol) {
    __shared__ float tf[32][65];
    int k0 = blockIdx.x * 32, n0 = blockIdx.y * 64;
    int t = threadIdx.x;
#pragma unroll
    for (int j = 0; j < 8; j++) {
        int idx = t + j * 256;
        int kr = idx >> 6, nc = idx & 63;
        tf[kr][nc] = dvec[k0 + kr] * R[(size_t)inact[k0 + kr] * NN + n0 + nc];
    }
    __syncthreads();
#pragma unroll
    for (int j = 0; j < 4; j++) {
        int idx = t + j * 256;
        int nr = idx >> 4, ku = idx & 15;
        float v0 = tf[2 * ku][nr], v1 = tf[2 * ku + 1][nr];
        u32 lo, hi = split2(v0, v1, lo);
        *(u32*)&oh[(size_t)(n0 + nr) * NN + k0 + 2 * ku] = hi;
        *(u32*)&ol[(size_t)(n0 + nr) * NN + k0 + 2 * ku] = lo;
    }
}

// ---------------- maps / reductions / outputs ---------------------------------
__global__ void k_maps0(int* colmap) {
    int t = blockIdx.x * 256 + threadIdx.x;
    colmap[t] = -1;
}
__global__ void k_maps1(const int* __restrict__ act, const int* __restrict__ inact,
                        int* winv, int* colmap) {
    int t = blockIdx.x * 256 + threadIdx.x;
    winv[inact[t]] = t;
    winv[act[t]]   = DIMV + t;
    colmap[act[t]] = t;
}

__global__ void k_dred(const float* __restrict__ gpart, float* __restrict__ dvec) {
    int j = blockIdx.x * 256 + threadIdx.x;
    float s = 0.f;
#pragma unroll
    for (int b = 0; b < 16; b++) s += gpart[b * DIMV + j];
    dvec[j] = s;
}

// grid NN + DIMV: blocks < NN fill D rows; blocks >= NN fill mc rows.
__global__ void __launch_bounds__(256) k_dfill(const float* __restrict__ Daa,
                                               const int* __restrict__ colmap,
                                               const int* __restrict__ winv,
                                               const float* __restrict__ dvec,
                                               float* __restrict__ D,
                                               float* __restrict__ mc) {
    int gr = blockIdx.x, t = threadIdx.x;
    if (gr >= NN) {
        int j = gr - NN;
        float* row = mc + (size_t)j * DIMV;
        ((float4*)row)[t] = make_float4(0.f, 0.f, 0.f, 0.f);
        __syncthreads();
        if (t == 0) row[j] = dvec[j];
        return;
    }
    int a = colmap[gr];
    float* row = D + (size_t)gr * NN;
    if (a < 0) {
        float4 z = make_float4(0.f, 0.f, 0.f, 0.f);
#pragma unroll
        for (int j = 0; j < 2; j++) ((float4*)row)[t + j * 256] = z;
        __syncthreads();
        if (t == 0) row[gr] = dvec[winv[gr]];
    } else {
        const float* dr = Daa + (size_t)a * DIMV;
#pragma unroll
        for (int j = 0; j < 8; j++) {
            int cc = t + j * 256;
            int cm = colmap[cc];
            row[cc] = (cm >= 0) ? dr[cm] : 0.f;
        }
    }
}

// ---------------- launch ------------------------------------------------------
extern "C" void kernel_launch(void* const* d_in, const int* in_sizes, int n_in,
                              void* d_out, int out_size) {
    const float* A    = (const float*)d_in[0];
    const float* O    = (const float*)d_in[1];
    const int*   idx  = (const int*)d_in[2];
    const int*   act  = (const int*)d_in[3];
    const int*   inact= (const int*)d_in[4];
    float* out = (float*)d_out;

    float *R, *dv, *gpart;
    int *winv, *colmap;
    bf16 *Ah, *Al, *Wh, *Wl, *T1ah, *T1al, *Dh, *Dl, *FTh, *FTl, *WTh, *WTl, *Bph, *Bpl;
    cudaGetSymbolAddress((void**)&R,     g_R);
    cudaGetSymbolAddress((void**)&dv,    g_d);
    cudaGetSymbolAddress((void**)&gpart, g_part);
    cudaGetSymbolAddress((void**)&winv,  g_winv);
    cudaGetSymbolAddress((void**)&colmap,g_colmap);
    cudaGetSymbolAddress((void**)&Ah,  g_Ah);   cudaGetSymbolAddress((void**)&Al,  g_Al);
    cudaGetSymbolAddress((void**)&Wh,  g_Wh);   cudaGetSymbolAddress((void**)&Wl,  g_Wl);
    cudaGetSymbolAddress((void**)&T1ah,g_T1ah); cudaGetSymbolAddress((void**)&T1al,g_T1al);
    cudaGetSymbolAddress((void**)&Dh,  g_Dh);   cudaGetSymbolAddress((void**)&Dl,  g_Dl);
    cudaGetSymbolAddress((void**)&FTh, g_FTh);  cudaGetSymbolAddress((void**)&FTl, g_FTl);
    cudaGetSymbolAddress((void**)&WTh, g_WTh);  cudaGetSymbolAddress((void**)&WTl, g_WTl);
    cudaGetSymbolAddress((void**)&Bph, g_Bph);  cudaGetSymbolAddress((void**)&Bpl, g_Bpl);

    const size_t NN2 = (size_t)NN * NN;
    float* o_arec  = out;
    float* o_right = out + NN2;
    float* o_D     = out + 2 * NN2;
    float* o_mc    = out + 3 * NN2;
    float* o_fc    = o_mc + (size_t)DIMV * DIMV;
    float* o_mw    = o_fc + (size_t)DIMV * DIMV;   // W fp32 = [Mi;Fa] contiguous

    const int smemR = 8 * NN * 2 * 4 + RWIN * 256 * 4 + RWIN * 16 * 4 + 8 * NN;
    cudaFuncSetAttribute(k_right, cudaFuncAttributeMaxDynamicSharedMemorySize, smemR);
    cudaFuncSetAttribute(k_mma<14>, cudaFuncAttributeMaxDynamicSharedMemorySize, SMG);
    cudaFuncSetAttribute(k_mma<3>,  cudaFuncAttributeMaxDynamicSharedMemorySize, SMG);
    cudaFuncSetAttribute(k_mma<2>,  cudaFuncAttributeMaxDynamicSharedMemorySize, SMG);
    cudaFuncSetAttribute(k_mma<17>, cudaFuncAttributeMaxDynamicSharedMemorySize, SMG);

    // 1. maps + A split
    k_maps0<<<NN / 256, 256>>>(colmap);
    k_maps1<<<DIMV / 256, 256>>>(act, inact, winv, colmap);
    k_conv<<<(int)(NN2 / 8 / 256), 256>>>(A, Ah, Al, (int)(NN2 / 8));

    // 2. right scan + fused prep
    k_right<<<NN / KK, 256, smemR>>>(O, idx);
    k_prep<<<NN, 256>>>(R, winv, o_right, o_mw, Wh, Wl);

    // 3. T1 = W @ A (A sym, NT). rows<1024: fused rowdot; rows>=1024: bf16 T1a
    k_mma<14><<<dim3(16, 16), 256, SMG>>>(Wh, Wl, NN, Ah, Al, NN, NN,
                                          nullptr, 0, T1ah, T1al, NN, o_mw, gpart);
    k_dred<<<DIMV / 256, 256>>>(gpart, dv);

    // 4. father_coefficients = D_aa = T1a @ Fa^T (fp32 -> o_fc, bf16 -> Dh/Dl)
    k_mma<3><<<dim3(8, 8), 256, SMG>>>(T1ah, T1al, NN,
                                       Wh + (size_t)DIMV * NN, Wl + (size_t)DIMV * NN, NN,
                                       NN, o_fc, DIMV, Dh, Dl, DIMV, nullptr, nullptr);

    // 5. FaT = Fa^T
    k_tbf<<<dim3(DIMV / 64, NN / 64), 256>>>(Wh + (size_t)DIMV * NN, Wl + (size_t)DIMV * NN,
                                             NN, FTh, FTl, DIMV);

    // 6. P = FaT @ D_aa (D_aa sym) -> B' right half
    k_mma<2><<<dim3(8, 16), 256, SMG>>>(FTh, FTl, DIMV, Dh, Dl, DIMV, DIMV,
                                        nullptr, 0, Bph + DIMV, Bpl + DIMV, NN,
                                        nullptr, nullptr);

    // 7. B' left half: d[k] * Mi[k][n]
    k_bpl<<<dim3(DIMV / 32, NN / 64), 256>>>(R, inact, dv, Bph, Bpl);

    // 8. WT = W^T
    k_tbf<<<dim3(NN / 64, NN / 64), 256>>>(Wh, Wl, NN, WTh, WTl, NN);

    // 9. A_rec = WT @ B'^T (symmetric: 136 lower-triangle tiles + mirror)
    k_mma<17><<<136, 256, SMG>>>(WTh, WTl, NN, Bph, Bpl, NN, NN,
                                 o_arec, NN, nullptr, nullptr, 0,
                                 nullptr, nullptr);

    // 10. D + mother_coefficients (one kernel)
    k_dfill<<<NN + DIMV, 256>>>(o_fc, colmap, winv, dv, o_D, o_mc);
}

// round 14
// speedup vs baseline: 1.0655x; 1.0062x over previous
#include <cuda_runtime.h>
#include <cuda_bf16.h>
#include <cstdint>

#define NN 2048
#define LL 512
#define KK 16
#define DIMV 1024

typedef unsigned int u32;
typedef __nv_bfloat16 bf16;

// ---------------- scratch (static device memory; no allocs allowed) ----------
__device__ float g_R [NN * NN];
__device__ float g_d [DIMV];
__device__ float g_part[16 * DIMV];
__device__ int   g_winv[NN];
__device__ int   g_colmap[NN];
__device__ bf16 g_Ah [NN * NN],    g_Al [NN * NN];
__device__ bf16 g_Wh [NN * NN],    g_Wl [NN * NN];
__device__ bf16 g_T1ah[DIMV * NN], g_T1al[DIMV * NN];
__device__ bf16 g_Dh [DIMV * DIMV], g_Dl [DIMV * DIMV];
__device__ bf16 g_FTh[NN * DIMV],  g_FTl[NN * DIMV];
__device__ bf16 g_WTh[NN * NN],    g_WTl[NN * NN];
__device__ bf16 g_Bph[NN * NN],    g_Bpl[NN * NN];

__device__ __forceinline__ u32 smem_u32(const void* p) {
    u32 a;
    asm("{ .reg .u64 t; cvta.to.shared.u64 t, %1; cvt.u32.u64 %0, t; }" : "=r"(a) : "l"(p));
    return a;
}

__device__ __forceinline__ u32 split2(float x, float y, u32& lo) {
    bf16 hx = __float2bfloat16(x), hy = __float2bfloat16(y);
    bf16 lx = __float2bfloat16(x - __bfloat162float(hx));
    bf16 ly = __float2bfloat16(y - __bfloat162float(hy));
    __nv_bfloat162 l2 = __halves2bfloat162(lx, ly);
    lo = *(u32*)&l2;
    __nv_bfloat162 h2 = __halves2bfloat162(hx, hy);
    return *(u32*)&h2;
}

#define LDS_F32(dst, addr) \
    asm volatile("ld.shared.f32 %0, [%1];" : "=f"(dst) : "r"(addr) : "memory")

// ---------------- right scan (R5 structure; asm-forced MLP-8 batched dot) -----
#define RWIN 8
__global__ void __launch_bounds__(256, 1) k_right(const float* __restrict__ Og,
                                                  const int* __restrict__ idxg) {
    extern __shared__ char smc[];
    float* Rt   = (float*)smc;                     // 8 slabs x NN x 2
    float* OsT  = Rt + 8 * NN * 2;                 // RWIN x 256 (transposed [k][i])
    int*   idsS = (int*)(OsT + RWIN * 256);        // RWIN x 16 (64B-aligned per step)
    char*  tch  = (char*)(idsS + RWIN * 16);       // 8 x NN

    const int tid = threadIdx.x, lane = tid & 31, w = tid >> 5;
    const int c0 = blockIdx.x * KK;
    float* wr = Rt + w * (NN * 2);
    char*  wt = tch + w * NN;

    for (int r = lane; r < NN; r += 32) { wr[r * 2] = 0.f; wr[r * 2 + 1] = 0.f; wt[r] = 0; }
    __syncwarp();
    if (lane < 2) {
        int gc = c0 + w * 2 + lane;
        wr[gc * 2 + lane] = 1.0f;
        wt[gc] = 1;
    }

    const int i = lane >> 1, c = lane & 1;
    const u32 wrA = smem_u32(wr) + (u32)c * 4;     // &wr[ids*2+c] = wrA + ids*8

    for (int w0 = 0; w0 < LL; w0 += RWIN) {
        __syncthreads();
#pragma unroll
        for (int s = 0; s < RWIN; s++) {
            int ii = tid >> 4, kk = tid & 15;
            OsT[s * 256 + kk * 16 + ii] = Og[(size_t)(w0 + s) * 256 + ii * 16 + kk];
        }
        if (tid < RWIN * 16) idsS[tid] = idxg[w0 * 16 + tid];
        __syncthreads();

        for (int s = 0; s < RWIN; s++) {
            const int* ids = idsS + s * 16;
            const float* Ot = OsT + s * 256;
            int myid = ids[lane & 15];
            bool hit = (lane < 16) && wt[myid];
            if (!__ballot_sync(0xffffffffu, hit)) continue;

            int ri = ids[i];                       // write index, issued early
            int4 q0 = ((const int4*)ids)[0];
            int4 q1 = ((const int4*)ids)[1];
            int4 q2 = ((const int4*)ids)[2];
            int4 q3 = ((const int4*)ids)[3];

            // batch 1: k = 0..7 (asm volatile keeps these loads grouped)
            float r0, r1, r2, r3, r4, r5, r6, r7;
            LDS_F32(r0, wrA + (u32)q0.x * 8);
            LDS_F32(r1, wrA + (u32)q0.y * 8);
            LDS_F32(r2, wrA + (u32)q0.z * 8);
            LDS_F32(r3, wrA + (u32)q0.w * 8);
            LDS_F32(r4, wrA + (u32)q1.x * 8);
            LDS_F32(r5, wrA + (u32)q1.y * 8);
            LDS_F32(r6, wrA + (u32)q1.z * 8);
            LDS_F32(r7, wrA + (u32)q1.w * 8);
            float y0 = Ot[0 * 16 + i] * r0 + Ot[4 * 16 + i] * r4;
            float y1 = Ot[1 * 16 + i] * r1 + Ot[5 * 16 + i] * r5;
            float y2 = Ot[2 * 16 + i] * r2 + Ot[6 * 16 + i] * r6;
            float y3 = Ot[3 * 16 + i] * r3 + Ot[7 * 16 + i] * r7;

            // batch 2: k = 8..15
            LDS_F32(r0, wrA + (u32)q2.x * 8);
            LDS_F32(r1, wrA + (u32)q2.y * 8);
            LDS_F32(r2, wrA + (u32)q2.z * 8);
            LDS_F32(r3, wrA + (u32)q2.w * 8);
            LDS_F32(r4, wrA + (u32)q3.x * 8);
            LDS_F32(r5, wrA + (u32)q3.y * 8);
            LDS_F32(r6, wrA + (u32)q3.z * 8);
            LDS_F32(r7, wrA + (u32)q3.w * 8);
            y0 += Ot[8 * 16 + i]  * r0 + Ot[12 * 16 + i] * r4;
            y1 += Ot[9 * 16 + i]  * r1 + Ot[13 * 16 + i] * r5;
            y2 += Ot[10 * 16 + i] * r2 + Ot[14 * 16 + i] * r6;
            y3 += Ot[11 * 16 + i] * r3 + Ot[15 * 16 + i] * r7;

            float y = (y0 + y1) + (y2 + y3);
            __syncwarp();
            wr[ri * 2 + c] = y;
            if (c == 0) wt[ri] = 1;
            __syncwarp();
        }
    }
    __syncthreads();
    {
        int cc = tid & 15;
        const float* slab = Rt + (cc >> 1) * (NN * 2);
        int sc = cc & 1;
        for (int r = tid >> 4; r < NN; r += 16)
            g_R[(size_t)r * NN + c0 + cc] = slab[r * 2 + sc];
    }
}

// ---------------- mma.sync bf16x3 GEMM: C[m,n] = sum_k A[m,k]*B[n,k] ---------
// 128x128 tile, 256 threads (2x4 warps, 64x32 each), K-chunk 32, 3-stage cp.async.
// EPI bits: 1=fp32 C, 2=bf16 hi/lo C, 4=bf16 only rows>=1024, 8=rowdot rows<1024,
//           16=symmetric C (lower-triangle linear grid + mirror writes).
#define PITCH 80
#define MATB  (128 * PITCH)
#define STAGE (4 * MATB)
#define SMG   (3 * STAGE + 2048)

__device__ __forceinline__ void mma_bf16(float* c, const u32* a, u32 b0, u32 b1) {
    asm volatile(
        "mma.sync.aligned.m16n8k16.row.col.f32.bf16.bf16.f32 "
        "{%0,%1,%2,%3}, {%4,%5,%6,%7}, {%8,%9}, {%0,%1,%2,%3};"
        : "+f"(c[0]), "+f"(c[1]), "+f"(c[2]), "+f"(c[3])
        : "r"(a[0]), "r"(a[1]), "r"(a[2]), "r"(a[3]), "r"(b0), "r"(b1));
}

template<int EPI>
__global__ __launch_bounds__(256, 1)
void k_mma(const bf16* __restrict__ Ah, const bf16* __restrict__ Al, int lda,
           const bf16* __restrict__ Bh, const bf16* __restrict__ Bl, int ldb,
           int K, float* __restrict__ Cf, int ldc,
           bf16* __restrict__ Ch, bf16* __restrict__ Cl, int ldch,
           const float* __restrict__ Wf, float* __restrict__ gpart) {
    extern __shared__ char sm[];
    const u32 sbase = smem_u32(sm);

    const int tid  = threadIdx.x;
    const int lane = tid & 31, warp = tid >> 5;
    const int wm = warp >> 2, wn = warp & 3;

    int bx, by;
    if (EPI & 16) {
        int t = blockIdx.x;
        by = (int)((sqrtf(8.0f * (float)t + 1.0f) - 1.0f) * 0.5f);
        while ((by + 1) * (by + 2) / 2 <= t) by++;
        while (by * (by + 1) / 2 > t) by--;
        bx = t - by * (by + 1) / 2;          // bx <= by
    } else {
        bx = blockIdx.x; by = blockIdx.y;
    }

    const int r0 = tid >> 2;
    const int sg = tid & 3;

    const bf16* gA[2] = { Ah, Al };
    const bf16* gB[2] = { Bh, Bl };

    auto issue_stage = [&](int buf, int kt) {
        u32 s = sbase + buf * STAGE;
#pragma unroll
        for (int h = 0; h < 2; h++) {
#pragma unroll
            for (int rr = 0; rr < 2; rr++) {
                int r = r0 + rr * 64;
                const void* srcA = gA[h] + (size_t)(by * 128 + r) * lda + kt + sg * 8;
                u32 dstA = s + h * MATB + r * PITCH + sg * 16;
                asm volatile("cp.async.cg.shared.global [%0], [%1], 16;"
                             :: "r"(dstA), "l"(srcA));
                const void* srcB = gB[h] + (size_t)(bx * 128 + r) * ldb + kt + sg * 8;
                u32 dstB = s + (2 + h) * MATB + r * PITCH + sg * 16;
                asm volatile("cp.async.cg.shared.global [%0], [%1], 16;"
                             :: "r"(dstB), "l"(srcB));
            }
        }
        asm volatile("cp.async.commit_group;" ::: "memory");
    };

    float acc[4][4][4];
#pragma unroll
    for (int mt = 0; mt < 4; mt++)
#pragma unroll
        for (int nt = 0; nt < 4; nt++)
#pragma unroll
            for (int j = 0; j < 4; j++) acc[mt][nt][j] = 0.0f;

    const int KT = K / 32;
    issue_stage(0, 0);
    issue_stage(1, 32);

    for (int c = 0; c < KT; c++) {
        if (c + 1 < KT) asm volatile("cp.async.wait_group 1;" ::: "memory");
        else            asm volatile("cp.async.wait_group 0;" ::: "memory");
        __syncthreads();
        if (c + 2 < KT) issue_stage((c + 2) % 3, (c + 2) * 32);
        const u32 s = sbase + (c % 3) * STAGE;

#pragma unroll
        for (int kh = 0; kh < 2; kh++) {
            const u32 lrow = (u32)(lane & 15) * PITCH + kh * 32 + (lane >> 4) * 16;
            u32 aF[2][4][4];
#pragma unroll
            for (int h = 0; h < 2; h++)
#pragma unroll
                for (int mt = 0; mt < 4; mt++) {
                    u32 ad = s + h * MATB + (u32)(wm * 64 + mt * 16) * PITCH + lrow;
                    asm volatile("ldmatrix.sync.aligned.m8n8.x4.shared.b16 "
                                 "{%0,%1,%2,%3}, [%4];"
                                 : "=r"(aF[h][mt][0]), "=r"(aF[h][mt][1]),
                                   "=r"(aF[h][mt][2]), "=r"(aF[h][mt][3]) : "r"(ad));
                }
            u32 bF[2][2][4];
#pragma unroll
            for (int h = 0; h < 2; h++)
#pragma unroll
                for (int np = 0; np < 2; np++) {
                    u32 ad = s + (2 + h) * MATB + (u32)(wn * 32 + np * 16) * PITCH + lrow;
                    asm volatile("ldmatrix.sync.aligned.m8n8.x4.shared.b16 "
                                 "{%0,%1,%2,%3}, [%4];"
                                 : "=r"(bF[h][np][0]), "=r"(bF[h][np][1]),
                                   "=r"(bF[h][np][2]), "=r"(bF[h][np][3]) : "r"(ad));
                }
#pragma unroll
            for (int mt = 0; mt < 4; mt++)
#pragma unroll
                for (int nt = 0; nt < 4; nt++) {
                    const int np = nt >> 1, sel = nt & 1;
                    u32 b0h = bF[0][np][sel], b1h = bF[0][np][sel + 2];
                    u32 b0l = bF[1][np][sel], b1l = bF[1][np][sel + 2];
                    mma_bf16(acc[mt][nt], aF[0][mt], b0h, b1h);
                    mma_bf16(acc[mt][nt], aF[0][mt], b0l, b1l);
                    mma_bf16(acc[mt][nt], aF[1][mt], b0h, b1h);
                }
        }
    }

    const int g = lane >> 2, tig = lane & 3;
    const bool dot = (EPI & 8) && (by < 8);

    if (!dot) {
#pragma unroll
        for (int mt = 0; mt < 4; mt++)
#pragma unroll
            for (int nt = 0; nt < 4; nt++)
#pragma unroll
                for (int hf = 0; hf < 2; hf++) {
                    int row = by * 128 + wm * 64 + mt * 16 + g + hf * 8;
                    int col = bx * 128 + wn * 32 + nt * 8 + tig * 2;
                    float v0 = acc[mt][nt][hf * 2], v1 = acc[mt][nt][hf * 2 + 1];
                    if (EPI & 1) {
                        float2* p = (float2*)(Cf + (size_t)row * ldc + col);
                        *p = make_float2(v0, v1);
                    }
                    if (EPI & 2) {
                        int br = row;
                        bool wv = true;
                        if (EPI & 4) { wv = (row >= DIMV); br = row - DIMV; }
                        if (wv) {
                            u32 lo, hi = split2(v0, v1, lo);
                            *(u32*)(Ch + (size_t)br * ldch + col) = hi;
                            *(u32*)(Cl + (size_t)br * ldch + col) = lo;
                        }
                    }
                }
        // mirror tile for symmetric output
        if ((EPI & 16) && bx != by) {
            float* ts = (float*)sm;                   // 128 x 129 floats
            __syncthreads();
#pragma unroll
            for (int mt = 0; mt < 4; mt++)
#pragma unroll
                for (int nt = 0; nt < 4; nt++)
#pragma unroll
                    for (int hf = 0; hf < 2; hf++) {
                        int rl = wm * 64 + mt * 16 + g + hf * 8;
                        int cl = wn * 32 + nt * 8 + tig * 2;
                        ts[(cl) * 129 + rl]     = acc[mt][nt][hf * 2];
                        ts[(cl + 1) * 129 + rl] = acc[mt][nt][hf * 2 + 1];
                    }
            __syncthreads();
            for (int e = tid; e < 128 * 32; e += 256) {
                int i = e >> 5, jq = e & 31;
                const float* src = &ts[i * 129 + jq * 4];
                float4 v = make_float4(src[0], src[1], src[2], src[3]);
                if (EPI & 1)
                    *(float4*)(Cf + (size_t)(bx * 128 + i) * ldc + by * 128 + jq * 4) = v;
                if (EPI & 2) {
                    u32 lo0, lo1;
                    u32 hi0 = split2(v.x, v.y, lo0);
                    u32 hi1 = split2(v.z, v.w, lo1);
                    *(uint2*)(Ch + (size_t)(bx * 128 + i) * ldch + by * 128 + jq * 4)
                        = make_uint2(hi0, hi1);
                    *(uint2*)(Cl + (size_t)(bx * 128 + i) * ldch + by * 128 + jq * 4)
                        = make_uint2(lo0, lo1);
                }
            }
        }
    } else {
        float rp[8];
#pragma unroll
        for (int q = 0; q < 8; q++) rp[q] = 0.f;
#pragma unroll
        for (int mt = 0; mt < 4; mt++)
#pragma unroll
            for (int hf = 0; hf < 2; hf++) {
                int row = by * 128 + wm * 64 + mt * 16 + g + hf * 8;
                const float* wrow = Wf + (size_t)row * NN;
#pragma unroll
                for (int nt = 0; nt < 4; nt++) {
                    int col = bx * 128 + wn * 32 + nt * 8 + tig * 2;
                    float2 wv = *(const float2*)(wrow + col);
                    rp[mt * 2 + hf] += acc[mt][nt][hf * 2] * wv.x
                                     + acc[mt][nt][hf * 2 + 1] * wv.y;
                }
            }
#pragma unroll
        for (int o = 1; o <= 2; o <<= 1)
#pragma unroll
            for (int q = 0; q < 8; q++)
                rp[q] += __shfl_xor_sync(0xffffffffu, rp[q], o);
        float* sred = (float*)(sm + 3 * STAGE);
        __syncthreads();
        if (tig == 0) {
#pragma unroll
            for (int mt = 0; mt < 4; mt++)
#pragma unroll
                for (int hf = 0; hf < 2; hf++) {
                    int rl = wm * 64 + mt * 16 + hf * 8 + g;
                    sred[rl * 4 + wn] = rp[mt * 2 + hf];
                }
        }
        __syncthreads();
        if (tid < 128) {
            float s2 = sred[tid * 4] + sred[tid * 4 + 1] + sred[tid * 4 + 2] + sred[tid * 4 + 3];
            gpart[bx * DIMV + by * 128 + tid] = s2;
        }
    }
}

// ---------------- fused prep: R row -> right, W fp32 (perm), Wh, Wl ----------
__global__ void __launch_bounds__(256) k_prep(const float* __restrict__ R,
                                              const int* __restrict__ winv,
                                              float* __restrict__ o_right,
                                              float* __restrict__ Wf,
                                              bf16* __restrict__ Wh,
                                              bf16* __restrict__ Wl) {
    int r = blockIdx.x, t = threadIdx.x;
    int p = winv[r];
    const float4* src = (const float4*)(R + (size_t)r * NN);
    float4* dr = (float4*)(o_right + (size_t)r * NN);
    float4* dw = (float4*)(Wf + (size_t)p * NN);
    uint2*  dh = (uint2*)(Wh + (size_t)p * NN);
    uint2*  dl = (uint2*)(Wl + (size_t)p * NN);
#pragma unroll
    for (int j = 0; j < 2; j++) {
        int k = t + j * 256;
        float4 v = src[k];
        dr[k] = v;
        dw[k] = v;
        u32 lo0, lo1;
        u32 hi0 = split2(v.x, v.y, lo0);
        u32 hi1 = split2(v.z, v.w, lo1);
        dh[k] = make_uint2(hi0, hi1);
        dl[k] = make_uint2(lo0, lo1);
    }
}

// ---------------- conv A -> bf16 hi/lo (8 elems/thread) -----------------------
__global__ void k_conv(const float* __restrict__ in, bf16* __restrict__ oh,
                       bf16* __restrict__ ol, int n8) {
    int t = blockIdx.x * 256 + threadIdx.x;
    if (t >= n8) return;
    float4 a = ((const float4*)in)[2 * t], b = ((const float4*)in)[2 * t + 1];
    u32 l0, l1, l2, l3;
    u32 h0 = split2(a.x, a.y, l0);
    u32 h1 = split2(a.z, a.w, l1);
    u32 h2 = split2(b.x, b.y, l2);
    u32 h3 = split2(b.z, b.w, l3);
    ((uint4*)oh)[t] = make_uint4(h0, h1, h2, h3);
    ((uint4*)ol)[t] = make_uint4(l0, l1, l2, l3);
}

// ---------------- bf16 hi/lo pair transpose: out[m][k] = in[k][m] -------------
__global__ void k_tbf(const bf16* __restrict__ ih, const bf16* __restrict__ il, int ldin,
                      bf16* __restrict__ oh, bf16* __restrict__ ol, int ldout) {
    __shared__ u32 th[64][33], tl[64][33];
    int k0 = blockIdx.x * 64, m0 = blockIdx.y * 64;
    int t = threadIdx.x;
#pragma unroll
    for (int j = 0; j < 8; j++) {
        int idx = t + j * 256;
        int kr = idx >> 5, mu = idx & 31;
        th[kr][mu] = *(const u32*)&ih[(size_t)(k0 + kr) * ldin + m0 + 2 * mu];
        tl[kr][mu] = *(const u32*)&il[(size_t)(k0 + kr) * ldin + m0 + 2 * mu];
    }
    __syncthreads();
#pragma unroll
    for (int j = 0; j < 8; j++) {
        int idx = t + j * 256;
        int mr = idx >> 5, ku = idx & 31;
        u32 u0 = th[2 * ku][mr >> 1], u1 = th[2 * ku + 1][mr >> 1];
        u32 v0 = tl[2 * ku][mr >> 1], v1 = tl[2 * ku + 1][mr >> 1];
        u32 sel = (mr & 1) ? 0x7632 : 0x5410;
        *(u32*)&oh[(size_t)(m0 + mr) * ldout + k0 + 2 * ku] = __byte_perm(u0, u1, sel);
        *(u32*)&ol[(size_t)(m0 + mr) * ldout + k0 + 2 * ku] = __byte_perm(v0, v1, sel);
    }
}

// ---------------- Bp left: Bp[n][k] = d[k] * R[inact[k]][n], bf16 split -------
__global__ void k_bpl(const float* __restrict__ R, const int* __restrict__ inact,
                      const float* __restrict__ dvec,
                      bf16* __restrict__ oh, bf16* __restrict__ ol) {
    __shared__ float tf[32][65];
    int k0 = blockIdx.x * 32, n0 = blockIdx.y * 64;
    int t = threadIdx.x;
#pragma unroll
    for (int j = 0; j < 8; j++) {
        int idx = t + j * 256;
        int kr = idx >> 6, nc = idx & 63;
        tf[kr][nc] = dvec[k0 + kr] * R[(size_t)inact[k0 + kr] * NN + n0 + nc];
    }
    __syncthreads();
#pragma unroll
    for (int j = 0; j < 4; j++) {
        int idx = t + j * 256;
        int nr = idx >> 4, ku = idx & 15;
        float v0 = tf[2 * ku][nr], v1 = tf[2 * ku + 1][nr];
        u32 lo, hi = split2(v0, v1, lo);
        *(u32*)&oh[(size_t)(n0 + nr) * NN + k0 + 2 * ku] = hi;
        *(u32*)&ol[(size_t)(n0 + nr) * NN + k0 + 2 * ku] = lo;
    }
}

// ---------------- maps / reductions / outputs ---------------------------------
__global__ void k_maps0(int* colmap) {
    int t = blockIdx.x * 256 + threadIdx.x;
    colmap[t] = -1;
}
__global__ void k_maps1(const int* __restrict__ act, const int* __restrict__ inact,
                        int* winv, int* colmap) {
    int t = blockIdx.x * 256 + threadIdx.x;
    winv[inact[t]] = t;
    winv[act[t]]   = DIMV + t;
    colmap[act[t]] = t;
}

__global__ void k_dred(const float* __restrict__ gpart, float* __restrict__ dvec) {
    int j = blockIdx.x * 256 + threadIdx.x;
    float s = 0.f;
#pragma unroll
    for (int b = 0; b < 16; b++) s += gpart[b * DIMV + j];
    dvec[j] = s;
}

// grid NN + DIMV: blocks < NN fill D rows; blocks >= NN fill mc rows.
__global__ void __launch_bounds__(256) k_dfill(const float* __restrict__ Daa,
                                               const int* __restrict__ colmap,
                                               const int* __restrict__ winv,
                                               const float* __restrict__ dvec,
                                               float* __restrict__ D,
                                               float* __restrict__ mc) {
    int gr = blockIdx.x, t = threadIdx.x;
    if (gr >= NN) {
        int j = gr - NN;
        float* row = mc + (size_t)j * DIMV;
        ((float4*)row)[t] = make_float4(0.f, 0.f, 0.f, 0.f);
        __syncthreads();
        if (t == 0) row[j] = dvec[j];
        return;
    }
    int a = colmap[gr];
    float* row = D + (size_t)gr * NN;
    if (a < 0) {
        float4 z = make_float4(0.f, 0.f, 0.f, 0.f);
#pragma unroll
        for (int j = 0; j < 2; j++) ((float4*)row)[t + j * 256] = z;
        __syncthreads();
        if (t == 0) row[gr] = dvec[winv[gr]];
    } else {
        const float* dr = Daa + (size_t)a * DIMV;
#pragma unroll
        for (int j = 0; j < 8; j++) {
            int cc = t + j * 256;
            int cm = colmap[cc];
            row[cc] = (cm >= 0) ? dr[cm] : 0.f;
        }
    }
}

// ---------------- launch ------------------------------------------------------
extern "C" void kernel_launch(void* const* d_in, const int* in_sizes, int n_in,
                              void* d_out, int out_size) {
    const float* A    = (const float*)d_in[0];
    const float* O    = (const float*)d_in[1];
    const int*   idx  = (const int*)d_in[2];
    const int*   act  = (const int*)d_in[3];
    const int*   inact= (const int*)d_in[4];
    float* out = (float*)d_out;

    float *R, *dv, *gpart;
    int *winv, *colmap;
    bf16 *Ah, *Al, *Wh, *Wl, *T1ah, *T1al, *Dh, *Dl, *FTh, *FTl, *WTh, *WTl, *Bph, *Bpl;
    cudaGetSymbolAddress((void**)&R,     g_R);
    cudaGetSymbolAddress((void**)&dv,    g_d);
    cudaGetSymbolAddress((void**)&gpart, g_part);
    cudaGetSymbolAddress((void**)&winv,  g_winv);
    cudaGetSymbolAddress((void**)&colmap,g_colmap);
    cudaGetSymbolAddress((void**)&Ah,  g_Ah);   cudaGetSymbolAddress((void**)&Al,  g_Al);
    cudaGetSymbolAddress((void**)&Wh,  g_Wh);   cudaGetSymbolAddress((void**)&Wl,  g_Wl);
    cudaGetSymbolAddress((void**)&T1ah,g_T1ah); cudaGetSymbolAddress((void**)&T1al,g_T1al);
    cudaGetSymbolAddress((void**)&Dh,  g_Dh);   cudaGetSymbolAddress((void**)&Dl,  g_Dl);
    cudaGetSymbolAddress((void**)&FTh, g_FTh);  cudaGetSymbolAddress((void**)&FTl, g_FTl);
    cudaGetSymbolAddress((void**)&WTh, g_WTh);  cudaGetSymbolAddress((void**)&WTl, g_WTl);
    cudaGetSymbolAddress((void**)&Bph, g_Bph);  cudaGetSymbolAddress((void**)&Bpl, g_Bpl);

    const size_t NN2 = (size_t)NN * NN;
    float* o_arec  = out;
    float* o_right = out + NN2;
    float* o_D     = out + 2 * NN2;
    float* o_mc    = out + 3 * NN2;
    float* o_fc    = o_mc + (size_t)DIMV * DIMV;
    float* o_mw    = o_fc + (size_t)DIMV * DIMV;   // W fp32 = [Mi;Fa] contiguous

    const int smemR = 8 * NN * 2 * 4 + RWIN * 256 * 4 + RWIN * 16 * 4 + 8 * NN;
    cudaFuncSetAttribute(k_right, cudaFuncAttributeMaxDynamicSharedMemorySize, smemR);
    cudaFuncSetAttribute(k_mma<14>, cudaFuncAttributeMaxDynamicSharedMemorySize, SMG);
    cudaFuncSetAttribute(k_mma<3>,  cudaFuncAttributeMaxDynamicSharedMemorySize, SMG);
    cudaFuncSetAttribute(k_mma<2>,  cudaFuncAttributeMaxDynamicSharedMemorySize, SMG);
    cudaFuncSetAttribute(k_mma<17>, cudaFuncAttributeMaxDynamicSharedMemorySize, SMG);

    // 1. maps + A split
    k_maps0<<<NN / 256, 256>>>(colmap);
    k_maps1<<<DIMV / 256, 256>>>(act, inact, winv, colmap);
    k_conv<<<(int)(NN2 / 8 / 256), 256>>>(A, Ah, Al, (int)(NN2 / 8));

    // 2. right scan + fused prep
    k_right<<<NN / KK, 256, smemR>>>(O, idx);
    k_prep<<<NN, 256>>>(R, winv, o_right, o_mw, Wh, Wl);

    // 3. T1 = W @ A (A sym, NT). rows<1024: fused rowdot; rows>=1024: bf16 T1a
    k_mma<14><<<dim3(16, 16), 256, SMG>>>(Wh, Wl, NN, Ah, Al, NN, NN,
                                          nullptr, 0, T1ah, T1al, NN, o_mw, gpart);
    k_dred<<<DIMV / 256, 256>>>(gpart, dv);

    // 4. father_coefficients = D_aa = T1a @ Fa^T (fp32 -> o_fc, bf16 -> Dh/Dl)
    k_mma<3><<<dim3(8, 8), 256, SMG>>>(T1ah, T1al, NN,
                                       Wh + (size_t)DIMV * NN, Wl + (size_t)DIMV * NN, NN,
                                       NN, o_fc, DIMV, Dh, Dl, DIMV, nullptr, nullptr);

    // 5. FaT = Fa^T
    k_tbf<<<dim3(DIMV / 64, NN / 64), 256>>>(Wh + (size_t)DIMV * NN, Wl + (size_t)DIMV * NN,
                                             NN, FTh, FTl, DIMV);

    // 6. P = FaT @ D_aa (D_aa sym) -> B' right half
    k_mma<2><<<dim3(8, 16), 256, SMG>>>(FTh, FTl, DIMV, Dh, Dl, DIMV, DIMV,
                                        nullptr, 0, Bph + DIMV, Bpl + DIMV, NN,
                                        nullptr, nullptr);

    // 7. B' left half: d[k] * Mi[k][n]
    k_bpl<<<dim3(DIMV / 32, NN / 64), 256>>>(R, inact, dv, Bph, Bpl);

    // 8. WT = W^T
    k_tbf<<<dim3(NN / 64, NN / 64), 256>>>(Wh, Wl, NN, WTh, WTl, NN);

    // 9. A_rec = WT @ B'^T (symmetric: 136 lower-triangle tiles + mirror)
    k_mma<17><<<136, 256, SMG>>>(WTh, WTl, NN, Bph, Bpl, NN, NN,
                                 o_arec, NN, nullptr, nullptr, 0,
                                 nullptr, nullptr);

    // 10. D + mother_coefficients (one kernel)
    k_dfill<<<NN + DIMV, 256>>>(o_fc, colmap, winv, dv, o_D, o_mc);
}

// round 15
// speedup vs baseline: 1.1586x; 1.0874x over previous
#include <cuda_runtime.h>
#include <cuda_bf16.h>
#include <cstdint>

#define NN 2048
#define LL 512
#define KK 16
#define DIMV 1024

typedef unsigned int u32;
typedef __nv_bfloat16 bf16;

// ---------------- scratch (static device memory; no allocs allowed) ----------
__device__ float g_R [NN * NN];
__device__ float g_d [DIMV];
__device__ float g_part[16 * DIMV];
__device__ int   g_winv[NN];
__device__ int   g_colmap[NN];
__device__ bf16 g_Ah [NN * NN],    g_Al [NN * NN];
__device__ bf16 g_Wh [NN * NN],    g_Wl [NN * NN];
__device__ bf16 g_T1ah[DIMV * NN], g_T1al[DIMV * NN];
__device__ bf16 g_Dh [DIMV * DIMV], g_Dl [DIMV * DIMV];
__device__ bf16 g_FTh[NN * DIMV],  g_FTl[NN * DIMV];
__device__ bf16 g_WTh[NN * NN],    g_WTl[NN * NN];   // also: split-K partials (8MB)
__device__ bf16 g_Bph[NN * NN],    g_Bpl[NN * NN];

__device__ __forceinline__ u32 smem_u32(const void* p) {
    u32 a;
    asm("{ .reg .u64 t; cvta.to.shared.u64 t, %1; cvt.u32.u64 %0, t; }" : "=r"(a) : "l"(p));
    return a;
}

__device__ __forceinline__ u32 split2(float x, float y, u32& lo) {
    bf16 hx = __float2bfloat16(x), hy = __float2bfloat16(y);
    bf16 lx = __float2bfloat16(x - __bfloat162float(hx));
    bf16 ly = __float2bfloat16(y - __bfloat162float(hy));
    __nv_bfloat162 l2 = __halves2bfloat162(lx, ly);
    lo = *(u32*)&l2;
    __nv_bfloat162 h2 = __halves2bfloat162(hx, hy);
    return *(u32*)&h2;
}

#define LDS_F32(dst, addr) \
    asm volatile("ld.shared.f32 %0, [%1];" : "=f"(dst) : "r"(addr) : "memory")

// ---------------- right scan (R14 version — frozen, ~152us) -------------------
#define RWIN 8
__global__ void __launch_bounds__(256, 1) k_right(const float* __restrict__ Og,
                                                  const int* __restrict__ idxg) {
    extern __shared__ char smc[];
    float* Rt   = (float*)smc;
    float* OsT  = Rt + 8 * NN * 2;
    int*   idsS = (int*)(OsT + RWIN * 256);
    char*  tch  = (char*)(idsS + RWIN * 16);

    const int tid = threadIdx.x, lane = tid & 31, w = tid >> 5;
    const int c0 = blockIdx.x * KK;
    float* wr = Rt + w * (NN * 2);
    char*  wt = tch + w * NN;

    for (int r = lane; r < NN; r += 32) { wr[r * 2] = 0.f; wr[r * 2 + 1] = 0.f; wt[r] = 0; }
    __syncwarp();
    if (lane < 2) {
        int gc = c0 + w * 2 + lane;
        wr[gc * 2 + lane] = 1.0f;
        wt[gc] = 1;
    }

    const int i = lane >> 1, c = lane & 1;
    const u32 wrA = smem_u32(wr) + (u32)c * 4;

    for (int w0 = 0; w0 < LL; w0 += RWIN) {
        __syncthreads();
#pragma unroll
        for (int s = 0; s < RWIN; s++) {
            int ii = tid >> 4, kk = tid & 15;
            OsT[s * 256 + kk * 16 + ii] = Og[(size_t)(w0 + s) * 256 + ii * 16 + kk];
        }
        if (tid < RWIN * 16) idsS[tid] = idxg[w0 * 16 + tid];
        __syncthreads();

        for (int s = 0; s < RWIN; s++) {
            const int* ids = idsS + s * 16;
            const float* Ot = OsT + s * 256;
            int myid = ids[lane & 15];
            bool hit = (lane < 16) && wt[myid];
            if (!__ballot_sync(0xffffffffu, hit)) continue;

            int ri = ids[i];
            int4 q0 = ((const int4*)ids)[0];
            int4 q1 = ((const int4*)ids)[1];
            int4 q2 = ((const int4*)ids)[2];
            int4 q3 = ((const int4*)ids)[3];

            float r0, r1, r2, r3, r4, r5, r6, r7;
            LDS_F32(r0, wrA + (u32)q0.x * 8);
            LDS_F32(r1, wrA + (u32)q0.y * 8);
            LDS_F32(r2, wrA + (u32)q0.z * 8);
            LDS_F32(r3, wrA + (u32)q0.w * 8);
            LDS_F32(r4, wrA + (u32)q1.x * 8);
            LDS_F32(r5, wrA + (u32)q1.y * 8);
            LDS_F32(r6, wrA + (u32)q1.z * 8);
            LDS_F32(r7, wrA + (u32)q1.w * 8);
            float y0 = Ot[0 * 16 + i] * r0 + Ot[4 * 16 + i] * r4;
            float y1 = Ot[1 * 16 + i] * r1 + Ot[5 * 16 + i] * r5;
            float y2 = Ot[2 * 16 + i] * r2 + Ot[6 * 16 + i] * r6;
            float y3 = Ot[3 * 16 + i] * r3 + Ot[7 * 16 + i] * r7;

            LDS_F32(r0, wrA + (u32)q2.x * 8);
            LDS_F32(r1, wrA + (u32)q2.y * 8);
            LDS_F32(r2, wrA + (u32)q2.z * 8);
            LDS_F32(r3, wrA + (u32)q2.w * 8);
            LDS_F32(r4, wrA + (u32)q3.x * 8);
            LDS_F32(r5, wrA + (u32)q3.y * 8);
            LDS_F32(r6, wrA + (u32)q3.z * 8);
            LDS_F32(r7, wrA + (u32)q3.w * 8);
            y0 += Ot[8 * 16 + i]  * r0 + Ot[12 * 16 + i] * r4;
            y1 += Ot[9 * 16 + i]  * r1 + Ot[13 * 16 + i] * r5;
            y2 += Ot[10 * 16 + i] * r2 + Ot[14 * 16 + i] * r6;
            y3 += Ot[11 * 16 + i] * r3 + Ot[15 * 16 + i] * r7;

            float y = (y0 + y1) + (y2 + y3);
            __syncwarp();
            wr[ri * 2 + c] = y;
            if (c == 0) wt[ri] = 1;
            __syncwarp();
        }
    }
    __syncthreads();
    {
        int cc = tid & 15;
        const float* slab = Rt + (cc >> 1) * (NN * 2);
        int sc = cc & 1;
        for (int r = tid >> 4; r < NN; r += 16)
            g_R[(size_t)r * NN + c0 + cc] = slab[r * 2 + sc];
    }
}

// ---------------- mma.sync bf16x3 GEMM: C[m,n] = sum_k A[m,k]*B[n,k] ---------
// 128x128 tile, 256 threads, K-chunk 32, 4-stage cp.async pipeline.
// EPI bits: 1=fp32 C, 2=bf16 hi/lo C, 4=bf16 only rows>=1024, 8=rowdot rows<1024,
//           16=symmetric C (triangle grid + mirror), 32=split-K by (by>>3).
#define PITCH 80
#define MATB  (128 * PITCH)
#define STAGE (4 * MATB)
#define SMG   (4 * STAGE + 2048)

__device__ __forceinline__ void mma_bf16(float* c, const u32* a, u32 b0, u32 b1) {
    asm volatile(
        "mma.sync.aligned.m16n8k16.row.col.f32.bf16.bf16.f32 "
        "{%0,%1,%2,%3}, {%4,%5,%6,%7}, {%8,%9}, {%0,%1,%2,%3};"
        : "+f"(c[0]), "+f"(c[1]), "+f"(c[2]), "+f"(c[3])
        : "r"(a[0]), "r"(a[1]), "r"(a[2]), "r"(a[3]), "r"(b0), "r"(b1));
}

template<int EPI>
__global__ __launch_bounds__(256, 1)
void k_mma(const bf16* __restrict__ Ah_, const bf16* __restrict__ Al_, int lda,
           const bf16* __restrict__ Bh_, const bf16* __restrict__ Bl_, int ldb,
           int K, float* __restrict__ Cf, int ldc,
           bf16* __restrict__ Ch, bf16* __restrict__ Cl, int ldch,
           const float* __restrict__ Wf, float* __restrict__ gpart) {
    extern __shared__ char sm[];
    const u32 sbase = smem_u32(sm);

    const int tid  = threadIdx.x;
    const int lane = tid & 31, warp = tid >> 5;
    const int wm = warp >> 2, wn = warp & 3;

    const bf16* Ah = Ah_; const bf16* Al = Al_;
    const bf16* Bh = Bh_; const bf16* Bl = Bl_;

    int bx, by;
    if (EPI & 16) {
        int t = blockIdx.x;
        by = (int)((sqrtf(8.0f * (float)t + 1.0f) - 1.0f) * 0.5f);
        while ((by + 1) * (by + 2) / 2 <= t) by++;
        while (by * (by + 1) / 2 > t) by--;
        bx = t - by * (by + 1) / 2;          // bx <= by
    } else {
        bx = blockIdx.x; by = blockIdx.y;
    }
    if (EPI & 32) {                          // split-K: by>>3 selects K-half
        int khalf = by >> 3;
        by &= 7;
        Ah += khalf * DIMV; Al += khalf * DIMV;
        Bh += khalf * DIMV; Bl += khalf * DIMV;
        Cf += (size_t)khalf * DIMV * DIMV;
    }

    const int r0 = tid >> 2;
    const int sg = tid & 3;

    const bf16* gA[2] = { Ah, Al };
    const bf16* gB[2] = { Bh, Bl };

    auto issue_stage = [&](int buf, int kt) {
        u32 s = sbase + buf * STAGE;
#pragma unroll
        for (int h = 0; h < 2; h++) {
#pragma unroll
            for (int rr = 0; rr < 2; rr++) {
                int r = r0 + rr * 64;
                const void* srcA = gA[h] + (size_t)(by * 128 + r) * lda + kt + sg * 8;
                u32 dstA = s + h * MATB + r * PITCH + sg * 16;
                asm volatile("cp.async.cg.shared.global [%0], [%1], 16;"
                             :: "r"(dstA), "l"(srcA));
                const void* srcB = gB[h] + (size_t)(bx * 128 + r) * ldb + kt + sg * 8;
                u32 dstB = s + (2 + h) * MATB + r * PITCH + sg * 16;
                asm volatile("cp.async.cg.shared.global [%0], [%1], 16;"
                             :: "r"(dstB), "l"(srcB));
            }
        }
        asm volatile("cp.async.commit_group;" ::: "memory");
    };

    float acc[4][4][4];
#pragma unroll
    for (int mt = 0; mt < 4; mt++)
#pragma unroll
        for (int nt = 0; nt < 4; nt++)
#pragma unroll
            for (int j = 0; j < 4; j++) acc[mt][nt][j] = 0.0f;

    const int KT = K / 32;
    issue_stage(0, 0);
    issue_stage(1, 32);
    issue_stage(2, 64);

    for (int c = 0; c < KT; c++) {
        if (c + 3 <= KT)      asm volatile("cp.async.wait_group 2;" ::: "memory");
        else if (c + 2 == KT) asm volatile("cp.async.wait_group 1;" ::: "memory");
        else                  asm volatile("cp.async.wait_group 0;" ::: "memory");
        __syncthreads();
        if (c + 3 < KT) issue_stage((c + 3) & 3, (c + 3) * 32);
        const u32 s = sbase + (c & 3) * STAGE;

#pragma unroll
        for (int kh = 0; kh < 2; kh++) {
            const u32 lrow = (u32)(lane & 15) * PITCH + kh * 32 + (lane >> 4) * 16;
            u32 aF[2][4][4];
#pragma unroll
            for (int h = 0; h < 2; h++)
#pragma unroll
                for (int mt = 0; mt < 4; mt++) {
                    u32 ad = s + h * MATB + (u32)(wm * 64 + mt * 16) * PITCH + lrow;
                    asm volatile("ldmatrix.sync.aligned.m8n8.x4.shared.b16 "
                                 "{%0,%1,%2,%3}, [%4];"
                                 : "=r"(aF[h][mt][0]), "=r"(aF[h][mt][1]),
                                   "=r"(aF[h][mt][2]), "=r"(aF[h][mt][3]) : "r"(ad));
                }
            u32 bF[2][2][4];
#pragma unroll
            for (int h = 0; h < 2; h++)
#pragma unroll
                for (int np = 0; np < 2; np++) {
                    u32 ad = s + (2 + h) * MATB + (u32)(wn * 32 + np * 16) * PITCH + lrow;
                    asm volatile("ldmatrix.sync.aligned.m8n8.x4.shared.b16 "
                                 "{%0,%1,%2,%3}, [%4];"
                                 : "=r"(bF[h][np][0]), "=r"(bF[h][np][1]),
                                   "=r"(bF[h][np][2]), "=r"(bF[h][np][3]) : "r"(ad));
                }
#pragma unroll
            for (int mt = 0; mt < 4; mt++)
#pragma unroll
                for (int nt = 0; nt < 4; nt++) {
                    const int np = nt >> 1, sel = nt & 1;
                    u32 b0h = bF[0][np][sel], b1h = bF[0][np][sel + 2];
                    u32 b0l = bF[1][np][sel], b1l = bF[1][np][sel + 2];
                    mma_bf16(acc[mt][nt], aF[0][mt], b0h, b1h);
                    mma_bf16(acc[mt][nt], aF[0][mt], b0l, b1l);
                    mma_bf16(acc[mt][nt], aF[1][mt], b0h, b1h);
                }
        }
    }

    const int g = lane >> 2, tig = lane & 3;
    const bool dot = (EPI & 8) && (by < 8);

    if (!dot) {
#pragma unroll
        for (int mt = 0; mt < 4; mt++)
#pragma unroll
            for (int nt = 0; nt < 4; nt++)
#pragma unroll
                for (int hf = 0; hf < 2; hf++) {
                    int row = by * 128 + wm * 64 + mt * 16 + g + hf * 8;
                    int col = bx * 128 + wn * 32 + nt * 8 + tig * 2;
                    float v0 = acc[mt][nt][hf * 2], v1 = acc[mt][nt][hf * 2 + 1];
                    if (EPI & 1) {
                        float2* p = (float2*)(Cf + (size_t)row * ldc + col);
                        *p = make_float2(v0, v1);
                    }
                    if (EPI & 2) {
                        int br = row;
                        bool wv = true;
                        if (EPI & 4) { wv = (row >= DIMV); br = row - DIMV; }
                        if (wv) {
                            u32 lo, hi = split2(v0, v1, lo);
                            *(u32*)(Ch + (size_t)br * ldch + col) = hi;
                            *(u32*)(Cl + (size_t)br * ldch + col) = lo;
                        }
                    }
                }
        // mirror tile for symmetric output
        if ((EPI & 16) && bx != by) {
            float* ts = (float*)sm;
            __syncthreads();
#pragma unroll
            for (int mt = 0; mt < 4; mt++)
#pragma unroll
                for (int nt = 0; nt < 4; nt++)
#pragma unroll
                    for (int hf = 0; hf < 2; hf++) {
                        int rl = wm * 64 + mt * 16 + g + hf * 8;
                        int cl = wn * 32 + nt * 8 + tig * 2;
                        ts[(cl) * 129 + rl]     = acc[mt][nt][hf * 2];
                        ts[(cl + 1) * 129 + rl] = acc[mt][nt][hf * 2 + 1];
                    }
            __syncthreads();
            for (int e = tid; e < 128 * 32; e += 256) {
                int i = e >> 5, jq = e & 31;
                const float* src = &ts[i * 129 + jq * 4];
                float4 v = make_float4(src[0], src[1], src[2], src[3]);
                if (EPI & 1)
                    *(float4*)(Cf + (size_t)(bx * 128 + i) * ldc + by * 128 + jq * 4) = v;
            }
        }
    } else {
        float rp[8];
#pragma unroll
        for (int q = 0; q < 8; q++) rp[q] = 0.f;
#pragma unroll
        for (int mt = 0; mt < 4; mt++)
#pragma unroll
            for (int hf = 0; hf < 2; hf++) {
                int row = by * 128 + wm * 64 + mt * 16 + g + hf * 8;
                const float* wrow = Wf + (size_t)row * NN;
#pragma unroll
                for (int nt = 0; nt < 4; nt++) {
                    int col = bx * 128 + wn * 32 + nt * 8 + tig * 2;
                    float2 wv = *(const float2*)(wrow + col);
                    rp[mt * 2 + hf] += acc[mt][nt][hf * 2] * wv.x
                                     + acc[mt][nt][hf * 2 + 1] * wv.y;
                }
            }
#pragma unroll
        for (int o = 1; o <= 2; o <<= 1)
#pragma unroll
            for (int q = 0; q < 8; q++)
                rp[q] += __shfl_xor_sync(0xffffffffu, rp[q], o);
        float* sred = (float*)(sm + 4 * STAGE);
        __syncthreads();
        if (tig == 0) {
#pragma unroll
            for (int mt = 0; mt < 4; mt++)
#pragma unroll
                for (int hf = 0; hf < 2; hf++) {
                    int rl = wm * 64 + mt * 16 + hf * 8 + g;
                    sred[rl * 4 + wn] = rp[mt * 2 + hf];
                }
        }
        __syncthreads();
        if (tid < 128) {
            float s2 = sred[tid * 4] + sred[tid * 4 + 1] + sred[tid * 4 + 2] + sred[tid * 4 + 3];
            gpart[bx * DIMV + by * 128 + tid] = s2;
        }
    }
}

// ---------------- split-K reduce: o_fc = P0+P1 (fp32) + Dh/Dl split -----------
__global__ void k_fcred(const float* __restrict__ P, float* __restrict__ fc,
                        bf16* __restrict__ Dh, bf16* __restrict__ Dl) {
    int j = blockIdx.x, t = threadIdx.x;         // j: row, t*4: col
    const float4 a = *(const float4*)(P + (size_t)j * DIMV + t * 4);
    const float4 b = *(const float4*)(P + (size_t)(DIMV + j) * DIMV + t * 4);
    float4 s = make_float4(a.x + b.x, a.y + b.y, a.z + b.z, a.w + b.w);
    *(float4*)(fc + (size_t)j * DIMV + t * 4) = s;
    u32 lo0, lo1;
    u32 hi0 = split2(s.x, s.y, lo0);
    u32 hi1 = split2(s.z, s.w, lo1);
    *(uint2*)(Dh + (size_t)j * DIMV + t * 4) = make_uint2(hi0, hi1);
    *(uint2*)(Dl + (size_t)j * DIMV + t * 4) = make_uint2(lo0, lo1);
}

// ---------------- fused prep: R row -> right, W fp32 (perm), Wh, Wl ----------
__global__ void __launch_bounds__(256) k_prep(const float* __restrict__ R,
                                              const int* __restrict__ winv,
                                              float* __restrict__ o_right,
                                              float* __restrict__ Wf,
                                              bf16* __restrict__ Wh,
                                              bf16* __restrict__ Wl) {
    int r = blockIdx.x, t = threadIdx.x;
    int p = winv[r];
    const float4* src = (const float4*)(R + (size_t)r * NN);
    float4* dr = (float4*)(o_right + (size_t)r * NN);
    float4* dw = (float4*)(Wf + (size_t)p * NN);
    uint2*  dh = (uint2*)(Wh + (size_t)p * NN);
    uint2*  dl = (uint2*)(Wl + (size_t)p * NN);
#pragma unroll
    for (int j = 0; j < 2; j++) {
        int k = t + j * 256;
        float4 v = src[k];
        dr[k] = v;
        dw[k] = v;
        u32 lo0, lo1;
        u32 hi0 = split2(v.x, v.y, lo0);
        u32 hi1 = split2(v.z, v.w, lo1);
        dh[k] = make_uint2(hi0, hi1);
        dl[k] = make_uint2(lo0, lo1);
    }
}

// ---------------- conv A -> bf16 hi/lo (8 elems/thread) -----------------------
__global__ void k_conv(const float* __restrict__ in, bf16* __restrict__ oh,
                       bf16* __restrict__ ol, int n8) {
    int t = blockIdx.x * 256 + threadIdx.x;
    if (t >= n8) return;
    float4 a = ((const float4*)in)[2 * t], b = ((const float4*)in)[2 * t + 1];
    u32 l0, l1, l2, l3;
    u32 h0 = split2(a.x, a.y, l0);
    u32 h1 = split2(a.z, a.w, l1);
    u32 h2 = split2(b.x, b.y, l2);
    u32 h3 = split2(b.z, b.w, l3);
    ((uint4*)oh)[t] = make_uint4(h0, h1, h2, h3);
    ((uint4*)ol)[t] = make_uint4(l0, l1, l2, l3);
}

// ---------------- bf16 hi/lo pair transpose: out[m][k] = in[k][m] -------------
__global__ void k_tbf(const bf16* __restrict__ ih, const bf16* __restrict__ il, int ldin,
                      bf16* __restrict__ oh, bf16* __restrict__ ol, int ldout) {
    __shared__ u32 th[64][33], tl[64][33];
    int k0 = blockIdx.x * 64, m0 = blockIdx.y * 64;
    int t = threadIdx.x;
#pragma unroll
    for (int j = 0; j < 8; j++) {
        int idx = t + j * 256;
        int kr = idx >> 5, mu = idx & 31;
        th[kr][mu] = *(const u32*)&ih[(size_t)(k0 + kr) * ldin + m0 + 2 * mu];
        tl[kr][mu] = *(const u32*)&il[(size_t)(k0 + kr) * ldin + m0 + 2 * mu];
    }
    __syncthreads();
#pragma unroll
    for (int j = 0; j < 8; j++) {
        int idx = t + j * 256;
        int mr = idx >> 5, ku = idx & 31;
        u32 u0 = th[2 * ku][mr >> 1], u1 = th[2 * ku + 1][mr >> 1];
        u32 v0 = tl[2 * ku][mr >> 1], v1 = tl[2 * ku + 1][mr >> 1];
        u32 sel = (mr & 1) ? 0x7632 : 0x5410;
        *(u32*)&oh[(size_t)(m0 + mr) * ldout + k0 + 2 * ku] = __byte_perm(u0, u1, sel);
        *(u32*)&ol[(size_t)(m0 + mr) * ldout + k0 + 2 * ku] = __byte_perm(v0, v1, sel);
    }
}

// ---------------- Bp left: Bp[n][k] = d[k] * R[inact[k]][n], bf16 split -------
__global__ void k_bpl(const float* __restrict__ R, const int* __restrict__ inact,
                      const float* __restrict__ dvec,
                      bf16* __restrict__ oh, bf16* __restrict__ ol) {
    __shared__ float tf[32][65];
    int k0 = blockIdx.x * 32, n0 = blockIdx.y * 64;
    int t = threadIdx.x;
#pragma unroll
    for (int j = 0; j < 8; j++) {
        int idx = t + j * 256;
        int kr = idx >> 6, nc = idx & 63;
        tf[kr][nc] = dvec[k0 + kr] * R[(size_t)inact[k0 + kr] * NN + n0 + nc];
    }
    __syncthreads();
#pragma unroll
    for (int j = 0; j < 4; j++) {
        int idx = t + j * 256;
        int nr = idx >> 4, ku = idx & 15;
        float v0 = tf[2 * ku][nr], v1 = tf[2 * ku + 1][nr];
        u32 lo, hi = split2(v0, v1, lo);
        *(u32*)&oh[(size_t)(n0 + nr) * NN + k0 + 2 * ku] = hi;
        *(u32*)&ol[(size_t)(n0 + nr) * NN + k0 + 2 * ku] = lo;
    }
}

// ---------------- maps (merged) / reductions / outputs ------------------------
__global__ void k_maps(const int* __restrict__ act, const int* __restrict__ inact,
                       int* winv, int* colmap) {
    int t = threadIdx.x;                     // 1 block x 1024
    colmap[t] = -1;
    colmap[t + 1024] = -1;
    __syncthreads();
    winv[inact[t]] = t;
    winv[act[t]]   = DIMV + t;
    colmap[act[t]] = t;
}

__global__ void k_dred(const float* __restrict__ gpart, float* __restrict__ dvec) {
    int j = blockIdx.x * 256 + threadIdx.x;
    float s = 0.f;
#pragma unroll
    for (int b = 0; b < 16; b++) s += gpart[b * DIMV + j];
    dvec[j] = s;
}

// grid NN + DIMV: blocks < NN fill D rows; blocks >= NN fill mc rows.
__global__ void __launch_bounds__(256) k_dfill(const float* __restrict__ Daa,
                                               const int* __restrict__ colmap,
                                               const int* __restrict__ winv,
                                               const float* __restrict__ dvec,
                                               float* __restrict__ D,
                                               float* __restrict__ mc) {
    int gr = blockIdx.x, t = threadIdx.x;
    if (gr >= NN) {
        int j = gr - NN;
        float* row = mc + (size_t)j * DIMV;
        ((float4*)row)[t] = make_float4(0.f, 0.f, 0.f, 0.f);
        __syncthreads();
        if (t == 0) row[j] = dvec[j];
        return;
    }
    int a = colmap[gr];
    float* row = D + (size_t)gr * NN;
    if (a < 0) {
        float4 z = make_float4(0.f, 0.f, 0.f, 0.f);
#pragma unroll
        for (int j = 0; j < 2; j++) ((float4*)row)[t + j * 256] = z;
        __syncthreads();
        if (t == 0) row[gr] = dvec[winv[gr]];
    } else {
        const float* dr = Daa + (size_t)a * DIMV;
#pragma unroll
        for (int j = 0; j < 8; j++) {
            int cc = t + j * 256;
            int cm = colmap[cc];
            row[cc] = (cm >= 0) ? dr[cm] : 0.f;
        }
    }
}

// ---------------- launch ------------------------------------------------------
extern "C" void kernel_launch(void* const* d_in, const int* in_sizes, int n_in,
                              void* d_out, int out_size) {
    const float* A    = (const float*)d_in[0];
    const float* O    = (const float*)d_in[1];
    const int*   idx  = (const int*)d_in[2];
    const int*   act  = (const int*)d_in[3];
    const int*   inact= (const int*)d_in[4];
    float* out = (float*)d_out;

    float *R, *dv, *gpart;
    int *winv, *colmap;
    bf16 *Ah, *Al, *Wh, *Wl, *T1ah, *T1al, *Dh, *Dl, *FTh, *FTl, *WTh, *WTl, *Bph, *Bpl;
    cudaGetSymbolAddress((void**)&R,     g_R);
    cudaGetSymbolAddress((void**)&dv,    g_d);
    cudaGetSymbolAddress((void**)&gpart, g_part);
    cudaGetSymbolAddress((void**)&winv,  g_winv);
    cudaGetSymbolAddress((void**)&colmap,g_colmap);
    cudaGetSymbolAddress((void**)&Ah,  g_Ah);   cudaGetSymbolAddress((void**)&Al,  g_Al);
    cudaGetSymbolAddress((void**)&Wh,  g_Wh);   cudaGetSymbolAddress((void**)&Wl,  g_Wl);
    cudaGetSymbolAddress((void**)&T1ah,g_T1ah); cudaGetSymbolAddress((void**)&T1al,g_T1al);
    cudaGetSymbolAddress((void**)&Dh,  g_Dh);   cudaGetSymbolAddress((void**)&Dl,  g_Dl);
    cudaGetSymbolAddress((void**)&FTh, g_FTh);  cudaGetSymbolAddress((void**)&FTl, g_FTl);
    cudaGetSymbolAddress((void**)&WTh, g_WTh);  cudaGetSymbolAddress((void**)&WTl, g_WTl);
    cudaGetSymbolAddress((void**)&Bph, g_Bph);  cudaGetSymbolAddress((void**)&Bpl, g_Bpl);

    float* Pk = (float*)WTh;                   // split-K partials (8MB, free until WT)

    const size_t NN2 = (size_t)NN * NN;
    float* o_arec  = out;
    float* o_right = out + NN2;
    float* o_D     = out + 2 * NN2;
    float* o_mc    = out + 3 * NN2;
    float* o_fc    = o_mc + (size_t)DIMV * DIMV;
    float* o_mw    = o_fc + (size_t)DIMV * DIMV;   // W fp32 = [Mi;Fa] contiguous

    const int smemR = 8 * NN * 2 * 4 + RWIN * 256 * 4 + RWIN * 16 * 4 + 8 * NN;
    cudaFuncSetAttribute(k_right, cudaFuncAttributeMaxDynamicSharedMemorySize, smemR);
    cudaFuncSetAttribute(k_mma<14>, cudaFuncAttributeMaxDynamicSharedMemorySize, SMG);
    cudaFuncSetAttribute(k_mma<33>, cudaFuncAttributeMaxDynamicSharedMemorySize, SMG);
    cudaFuncSetAttribute(k_mma<2>,  cudaFuncAttributeMaxDynamicSharedMemorySize, SMG);
    cudaFuncSetAttribute(k_mma<17>, cudaFuncAttributeMaxDynamicSharedMemorySize, SMG);

    // 1. maps + A split
    k_maps<<<1, 1024>>>(act, inact, winv, colmap);
    k_conv<<<(int)(NN2 / 8 / 256), 256>>>(A, Ah, Al, (int)(NN2 / 8));

    // 2. right scan + fused prep
    k_right<<<NN / KK, 256, smemR>>>(O, idx);
    k_prep<<<NN, 256>>>(R, winv, o_right, o_mw, Wh, Wl);

    // 3. T1 = W @ A (A sym, NT). rows<1024: fused rowdot; rows>=1024: bf16 T1a
    k_mma<14><<<dim3(16, 16), 256, SMG>>>(Wh, Wl, NN, Ah, Al, NN, NN,
                                          nullptr, 0, T1ah, T1al, NN, o_mw, gpart);
    k_dred<<<DIMV / 256, 256>>>(gpart, dv);

    // 4. D_aa = T1a @ Fa^T — split-K x2 (128 CTAs, one full wave), then reduce
    k_mma<33><<<dim3(8, 16), 256, SMG>>>(T1ah, T1al, NN,
                                         Wh + (size_t)DIMV * NN, Wl + (size_t)DIMV * NN, NN,
                                         DIMV, Pk, DIMV, nullptr, nullptr, 0,
                                         nullptr, nullptr);
    k_fcred<<<DIMV, 256>>>(Pk, o_fc, Dh, Dl);

    // 5. FaT = Fa^T
    k_tbf<<<dim3(DIMV / 64, NN / 64), 256>>>(Wh + (size_t)DIMV * NN, Wl + (size_t)DIMV * NN,
                                             NN, FTh, FTl, DIMV);

    // 6. P = FaT @ D_aa (D_aa sym) -> B' right half
    k_mma<2><<<dim3(8, 16), 256, SMG>>>(FTh, FTl, DIMV, Dh, Dl, DIMV, DIMV,
                                        nullptr, 0, Bph + DIMV, Bpl + DIMV, NN,
                                        nullptr, nullptr);

    // 7. B' left half: d[k] * Mi[k][n]
    k_bpl<<<dim3(DIMV / 32, NN / 64), 256>>>(R, inact, dv, Bph, Bpl);

    // 8. WT = W^T (overwrites split-K partials — safe, consumed by k_fcred)
    k_tbf<<<dim3(NN / 64, NN / 64), 256>>>(Wh, Wl, NN, WTh, WTl, NN);

    // 9. A_rec = WT @ B'^T (symmetric: 136 lower-triangle tiles + mirror)
    k_mma<17><<<136, 256, SMG>>>(WTh, WTl, NN, Bph, Bpl, NN, NN,
                                 o_arec, NN, nullptr, nullptr, 0,
                                 nullptr, nullptr);

    // 10. D + mother_coefficients (one kernel)
    k_dfill<<<NN + DIMV, 256>>>(o_fc, colmap, winv, dv, o_D, o_mc);
}

// round 16
// speedup vs baseline: 1.1742x; 1.0135x over previous
#include <cuda_runtime.h>
#include <cuda_bf16.h>
#include <cstdint>

#define NN 2048
#define LL 512
#define KK 16
#define DIMV 1024

typedef unsigned int u32;
typedef __nv_bfloat16 bf16;

// ---------------- scratch (static device memory; no allocs allowed) ----------
__device__ float g_R [NN * NN];
__device__ float g_d [DIMV];
__device__ float g_part[16 * DIMV];
__device__ float g_Pk [2 * DIMV * DIMV];   // split-K partials (dedicated)
__device__ int   g_winv[NN];
__device__ int   g_colmap[NN];
__device__ bf16 g_Ah [NN * NN],    g_Al [NN * NN];
__device__ bf16 g_Wh [NN * NN],    g_Wl [NN * NN];
__device__ bf16 g_T1ah[DIMV * NN], g_T1al[DIMV * NN];
__device__ bf16 g_Dh [DIMV * DIMV], g_Dl [DIMV * DIMV];
__device__ bf16 g_FTh[NN * DIMV],  g_FTl[NN * DIMV];
__device__ bf16 g_WTh[NN * NN],    g_WTl[NN * NN];
__device__ bf16 g_Bph[NN * NN],    g_Bpl[NN * NN];

__device__ __forceinline__ u32 smem_u32(const void* p) {
    u32 a;
    asm("{ .reg .u64 t; cvta.to.shared.u64 t, %1; cvt.u32.u64 %0, t; }" : "=r"(a) : "l"(p));
    return a;
}

__device__ __forceinline__ u32 split2(float x, float y, u32& lo) {
    bf16 hx = __float2bfloat16(x), hy = __float2bfloat16(y);
    bf16 lx = __float2bfloat16(x - __bfloat162float(hx));
    bf16 ly = __float2bfloat16(y - __bfloat162float(hy));
    __nv_bfloat162 l2 = __halves2bfloat162(lx, ly);
    lo = *(u32*)&l2;
    __nv_bfloat162 h2 = __halves2bfloat162(hx, hy);
    return *(u32*)&h2;
}

#define LDS_F32(dst, addr) \
    asm volatile("ld.shared.f32 %0, [%1];" : "=f"(dst) : "r"(addr) : "memory")

// ---------------- right scan (frozen, ~152us) ----------------------------------
#define RWIN 8
__global__ void __launch_bounds__(256, 1) k_right(const float* __restrict__ Og,
                                                  const int* __restrict__ idxg) {
    extern __shared__ char smc[];
    float* Rt   = (float*)smc;
    float* OsT  = Rt + 8 * NN * 2;
    int*   idsS = (int*)(OsT + RWIN * 256);
    char*  tch  = (char*)(idsS + RWIN * 16);

    const int tid = threadIdx.x, lane = tid & 31, w = tid >> 5;
    const int c0 = blockIdx.x * KK;
    float* wr = Rt + w * (NN * 2);
    char*  wt = tch + w * NN;

    for (int r = lane; r < NN; r += 32) { wr[r * 2] = 0.f; wr[r * 2 + 1] = 0.f; wt[r] = 0; }
    __syncwarp();
    if (lane < 2) {
        int gc = c0 + w * 2 + lane;
        wr[gc * 2 + lane] = 1.0f;
        wt[gc] = 1;
    }

    const int i = lane >> 1, c = lane & 1;
    const u32 wrA = smem_u32(wr) + (u32)c * 4;

    for (int w0 = 0; w0 < LL; w0 += RWIN) {
        __syncthreads();
#pragma unroll
        for (int s = 0; s < RWIN; s++) {
            int ii = tid >> 4, kk = tid & 15;
            OsT[s * 256 + kk * 16 + ii] = Og[(size_t)(w0 + s) * 256 + ii * 16 + kk];
        }
        if (tid < RWIN * 16) idsS[tid] = idxg[w0 * 16 + tid];
        __syncthreads();

        for (int s = 0; s < RWIN; s++) {
            const int* ids = idsS + s * 16;
            const float* Ot = OsT + s * 256;
            int myid = ids[lane & 15];
            bool hit = (lane < 16) && wt[myid];
            if (!__ballot_sync(0xffffffffu, hit)) continue;

            int ri = ids[i];
            int4 q0 = ((const int4*)ids)[0];
            int4 q1 = ((const int4*)ids)[1];
            int4 q2 = ((const int4*)ids)[2];
            int4 q3 = ((const int4*)ids)[3];

            float r0, r1, r2, r3, r4, r5, r6, r7;
            LDS_F32(r0, wrA + (u32)q0.x * 8);
            LDS_F32(r1, wrA + (u32)q0.y * 8);
            LDS_F32(r2, wrA + (u32)q0.z * 8);
            LDS_F32(r3, wrA + (u32)q0.w * 8);
            LDS_F32(r4, wrA + (u32)q1.x * 8);
            LDS_F32(r5, wrA + (u32)q1.y * 8);
            LDS_F32(r6, wrA + (u32)q1.z * 8);
            LDS_F32(r7, wrA + (u32)q1.w * 8);
            float y0 = Ot[0 * 16 + i] * r0 + Ot[4 * 16 + i] * r4;
            float y1 = Ot[1 * 16 + i] * r1 + Ot[5 * 16 + i] * r5;
            float y2 = Ot[2 * 16 + i] * r2 + Ot[6 * 16 + i] * r6;
            float y3 = Ot[3 * 16 + i] * r3 + Ot[7 * 16 + i] * r7;

            LDS_F32(r0, wrA + (u32)q2.x * 8);
            LDS_F32(r1, wrA + (u32)q2.y * 8);
            LDS_F32(r2, wrA + (u32)q2.z * 8);
            LDS_F32(r3, wrA + (u32)q2.w * 8);
            LDS_F32(r4, wrA + (u32)q3.x * 8);
            LDS_F32(r5, wrA + (u32)q3.y * 8);
            LDS_F32(r6, wrA + (u32)q3.z * 8);
            LDS_F32(r7, wrA + (u32)q3.w * 8);
            y0 += Ot[8 * 16 + i]  * r0 + Ot[12 * 16 + i] * r4;
            y1 += Ot[9 * 16 + i]  * r1 + Ot[13 * 16 + i] * r5;
            y2 += Ot[10 * 16 + i] * r2 + Ot[14 * 16 + i] * r6;
            y3 += Ot[11 * 16 + i] * r3 + Ot[15 * 16 + i] * r7;

            float y = (y0 + y1) + (y2 + y3);
            __syncwarp();
            wr[ri * 2 + c] = y;
            if (c == 0) wt[ri] = 1;
            __syncwarp();
        }
    }
    __syncthreads();
    {
        int cc = tid & 15;
        const float* slab = Rt + (cc >> 1) * (NN * 2);
        int sc = cc & 1;
        for (int r = tid >> 4; r < NN; r += 16)
            g_R[(size_t)r * NN + c0 + cc] = slab[r * 2 + sc];
    }
}

// ---------------- mma.sync bf16x3 GEMM (R15 core, 4-stage) --------------------
#define PITCH 80
#define MATB  (128 * PITCH)
#define STAGE (4 * MATB)
#define SMG   (4 * STAGE + 2048)

__device__ __forceinline__ void mma_bf16(float* c, const u32* a, u32 b0, u32 b1) {
    asm volatile(
        "mma.sync.aligned.m16n8k16.row.col.f32.bf16.bf16.f32 "
        "{%0,%1,%2,%3}, {%4,%5,%6,%7}, {%8,%9}, {%0,%1,%2,%3};"
        : "+f"(c[0]), "+f"(c[1]), "+f"(c[2]), "+f"(c[3])
        : "r"(a[0]), "r"(a[1]), "r"(a[2]), "r"(a[3]), "r"(b0), "r"(b1));
}

template<int EPI>
__global__ __launch_bounds__(256, 1)
void k_mma(const bf16* __restrict__ Ah_, const bf16* __restrict__ Al_, int lda,
           const bf16* __restrict__ Bh_, const bf16* __restrict__ Bl_, int ldb,
           int K, float* __restrict__ Cf, int ldc,
           bf16* __restrict__ Ch, bf16* __restrict__ Cl, int ldch,
           const float* __restrict__ Wf, float* __restrict__ gpart) {
    extern __shared__ char sm[];
    const u32 sbase = smem_u32(sm);

    const int tid  = threadIdx.x;
    const int lane = tid & 31, warp = tid >> 5;
    const int wm = warp >> 2, wn = warp & 3;

    const bf16* Ah = Ah_; const bf16* Al = Al_;
    const bf16* Bh = Bh_; const bf16* Bl = Bl_;

    int bx, by;
    if (EPI & 16) {
        int t = blockIdx.x;
        by = (int)((sqrtf(8.0f * (float)t + 1.0f) - 1.0f) * 0.5f);
        while ((by + 1) * (by + 2) / 2 <= t) by++;
        while (by * (by + 1) / 2 > t) by--;
        bx = t - by * (by + 1) / 2;
    } else {
        bx = blockIdx.x; by = blockIdx.y;
    }
    if (EPI & 32) {
        int khalf = by >> 3;
        by &= 7;
        Ah += khalf * DIMV; Al += khalf * DIMV;
        Bh += khalf * DIMV; Bl += khalf * DIMV;
        Cf += (size_t)khalf * DIMV * DIMV;
    }

    const int r0 = tid >> 2;
    const int sg = tid & 3;

    const bf16* gA[2] = { Ah, Al };
    const bf16* gB[2] = { Bh, Bl };

    auto issue_stage = [&](int buf, int kt) {
        u32 s = sbase + buf * STAGE;
#pragma unroll
        for (int h = 0; h < 2; h++) {
#pragma unroll
            for (int rr = 0; rr < 2; rr++) {
                int r = r0 + rr * 64;
                const void* srcA = gA[h] + (size_t)(by * 128 + r) * lda + kt + sg * 8;
                u32 dstA = s + h * MATB + r * PITCH + sg * 16;
                asm volatile("cp.async.cg.shared.global [%0], [%1], 16;"
                             :: "r"(dstA), "l"(srcA));
                const void* srcB = gB[h] + (size_t)(bx * 128 + r) * ldb + kt + sg * 8;
                u32 dstB = s + (2 + h) * MATB + r * PITCH + sg * 16;
                asm volatile("cp.async.cg.shared.global [%0], [%1], 16;"
                             :: "r"(dstB), "l"(srcB));
            }
        }
        asm volatile("cp.async.commit_group;" ::: "memory");
    };

    float acc[4][4][4];
#pragma unroll
    for (int mt = 0; mt < 4; mt++)
#pragma unroll
        for (int nt = 0; nt < 4; nt++)
#pragma unroll
            for (int j = 0; j < 4; j++) acc[mt][nt][j] = 0.0f;

    const int KT = K / 32;
    issue_stage(0, 0);
    issue_stage(1, 32);
    issue_stage(2, 64);

    for (int c = 0; c < KT; c++) {
        if (c + 3 <= KT)      asm volatile("cp.async.wait_group 2;" ::: "memory");
        else if (c + 2 == KT) asm volatile("cp.async.wait_group 1;" ::: "memory");
        else                  asm volatile("cp.async.wait_group 0;" ::: "memory");
        __syncthreads();
        if (c + 3 < KT) issue_stage((c + 3) & 3, (c + 3) * 32);
        const u32 s = sbase + (c & 3) * STAGE;

#pragma unroll
        for (int kh = 0; kh < 2; kh++) {
            const u32 lrow = (u32)(lane & 15) * PITCH + kh * 32 + (lane >> 4) * 16;
            u32 aF[2][4][4];
#pragma unroll
            for (int h = 0; h < 2; h++)
#pragma unroll
                for (int mt = 0; mt < 4; mt++) {
                    u32 ad = s + h * MATB + (u32)(wm * 64 + mt * 16) * PITCH + lrow;
                    asm volatile("ldmatrix.sync.aligned.m8n8.x4.shared.b16 "
                                 "{%0,%1,%2,%3}, [%4];"
                                 : "=r"(aF[h][mt][0]), "=r"(aF[h][mt][1]),
                                   "=r"(aF[h][mt][2]), "=r"(aF[h][mt][3]) : "r"(ad));
                }
            u32 bF[2][2][4];
#pragma unroll
            for (int h = 0; h < 2; h++)
#pragma unroll
                for (int np = 0; np < 2; np++) {
                    u32 ad = s + (2 + h) * MATB + (u32)(wn * 32 + np * 16) * PITCH + lrow;
                    asm volatile("ldmatrix.sync.aligned.m8n8.x4.shared.b16 "
                                 "{%0,%1,%2,%3}, [%4];"
                                 : "=r"(bF[h][np][0]), "=r"(bF[h][np][1]),
                                   "=r"(bF[h][np][2]), "=r"(bF[h][np][3]) : "r"(ad));
                }
#pragma unroll
            for (int mt = 0; mt < 4; mt++)
#pragma unroll
                for (int nt = 0; nt < 4; nt++) {
                    const int np = nt >> 1, sel = nt & 1;
                    u32 b0h = bF[0][np][sel], b1h = bF[0][np][sel + 2];
                    u32 b0l = bF[1][np][sel], b1l = bF[1][np][sel + 2];
                    mma_bf16(acc[mt][nt], aF[0][mt], b0h, b1h);
                    mma_bf16(acc[mt][nt], aF[0][mt], b0l, b1l);
                    mma_bf16(acc[mt][nt], aF[1][mt], b0h, b1h);
                }
        }
    }

    const int g = lane >> 2, tig = lane & 3;
    const bool dot = (EPI & 8) && (by < 8);

    if (!dot) {
#pragma unroll
        for (int mt = 0; mt < 4; mt++)
#pragma unroll
            for (int nt = 0; nt < 4; nt++)
#pragma unroll
                for (int hf = 0; hf < 2; hf++) {
                    int row = by * 128 + wm * 64 + mt * 16 + g + hf * 8;
                    int col = bx * 128 + wn * 32 + nt * 8 + tig * 2;
                    float v0 = acc[mt][nt][hf * 2], v1 = acc[mt][nt][hf * 2 + 1];
                    if (EPI & 1) {
                        float2* p = (float2*)(Cf + (size_t)row * ldc + col);
                        *p = make_float2(v0, v1);
                    }
                    if (EPI & 2) {
                        int br = row;
                        bool wv = true;
                        if (EPI & 4) { wv = (row >= DIMV); br = row - DIMV; }
                        if (wv) {
                            u32 lo, hi = split2(v0, v1, lo);
                            *(u32*)(Ch + (size_t)br * ldch + col) = hi;
                            *(u32*)(Cl + (size_t)br * ldch + col) = lo;
                        }
                    }
                }
        if ((EPI & 16) && bx != by) {
            float* ts = (float*)sm;
            __syncthreads();
#pragma unroll
            for (int mt = 0; mt < 4; mt++)
#pragma unroll
                for (int nt = 0; nt < 4; nt++)
#pragma unroll
                    for (int hf = 0; hf < 2; hf++) {
                        int rl = wm * 64 + mt * 16 + g + hf * 8;
                        int cl = wn * 32 + nt * 8 + tig * 2;
                        ts[(cl) * 129 + rl]     = acc[mt][nt][hf * 2];
                        ts[(cl + 1) * 129 + rl] = acc[mt][nt][hf * 2 + 1];
                    }
            __syncthreads();
            for (int e = tid; e < 128 * 32; e += 256) {
                int i = e >> 5, jq = e & 31;
                const float* src = &ts[i * 129 + jq * 4];
                float4 v = make_float4(src[0], src[1], src[2], src[3]);
                if (EPI & 1)
                    *(float4*)(Cf + (size_t)(bx * 128 + i) * ldc + by * 128 + jq * 4) = v;
            }
        }
    } else {
        float rp[8];
#pragma unroll
        for (int q = 0; q < 8; q++) rp[q] = 0.f;
#pragma unroll
        for (int mt = 0; mt < 4; mt++)
#pragma unroll
            for (int hf = 0; hf < 2; hf++) {
                int row = by * 128 + wm * 64 + mt * 16 + g + hf * 8;
                const float* wrow = Wf + (size_t)row * NN;
#pragma unroll
                for (int nt = 0; nt < 4; nt++) {
                    int col = bx * 128 + wn * 32 + nt * 8 + tig * 2;
                    float2 wv = *(const float2*)(wrow + col);
                    rp[mt * 2 + hf] += acc[mt][nt][hf * 2] * wv.x
                                     + acc[mt][nt][hf * 2 + 1] * wv.y;
                }
            }
#pragma unroll
        for (int o = 1; o <= 2; o <<= 1)
#pragma unroll
            for (int q = 0; q < 8; q++)
                rp[q] += __shfl_xor_sync(0xffffffffu, rp[q], o);
        float* sred = (float*)(sm + 4 * STAGE);
        __syncthreads();
        if (tig == 0) {
#pragma unroll
            for (int mt = 0; mt < 4; mt++)
#pragma unroll
                for (int hf = 0; hf < 2; hf++) {
                    int rl = wm * 64 + mt * 16 + hf * 8 + g;
                    sred[rl * 4 + wn] = rp[mt * 2 + hf];
                }
        }
        __syncthreads();
        if (tid < 128) {
            float s2 = sred[tid * 4] + sred[tid * 4 + 1] + sred[tid * 4 + 2] + sred[tid * 4 + 3];
            gpart[bx * DIMV + by * 128 + tid] = s2;
        }
    }
}

// ---------------- split-K reduce: o_fc = P0+P1 + Dh/Dl split -------------------
__global__ void k_fcred(const float* __restrict__ P, float* __restrict__ fc,
                        bf16* __restrict__ Dh, bf16* __restrict__ Dl) {
    int j = blockIdx.x, t = threadIdx.x;
    const float4 a = *(const float4*)(P + (size_t)j * DIMV + t * 4);
    const float4 b = *(const float4*)(P + (size_t)(DIMV + j) * DIMV + t * 4);
    float4 s = make_float4(a.x + b.x, a.y + b.y, a.z + b.z, a.w + b.w);
    *(float4*)(fc + (size_t)j * DIMV + t * 4) = s;
    u32 lo0, lo1;
    u32 hi0 = split2(s.x, s.y, lo0);
    u32 hi1 = split2(s.z, s.w, lo1);
    *(uint2*)(Dh + (size_t)j * DIMV + t * 4) = make_uint2(hi0, hi1);
    *(uint2*)(Dl + (size_t)j * DIMV + t * 4) = make_uint2(lo0, lo1);
}

// ---------------- fused prep ---------------------------------------------------
__global__ void __launch_bounds__(256) k_prep(const float* __restrict__ R,
                                              const int* __restrict__ winv,
                                              float* __restrict__ o_right,
                                              float* __restrict__ Wf,
                                              bf16* __restrict__ Wh,
                                              bf16* __restrict__ Wl) {
    int r = blockIdx.x, t = threadIdx.x;
    int p = winv[r];
    const float4* src = (const float4*)(R + (size_t)r * NN);
    float4* dr = (float4*)(o_right + (size_t)r * NN);
    float4* dw = (float4*)(Wf + (size_t)p * NN);
    uint2*  dh = (uint2*)(Wh + (size_t)p * NN);
    uint2*  dl = (uint2*)(Wl + (size_t)p * NN);
#pragma unroll
    for (int j = 0; j < 2; j++) {
        int k = t + j * 256;
        float4 v = src[k];
        dr[k] = v;
        dw[k] = v;
        u32 lo0, lo1;
        u32 hi0 = split2(v.x, v.y, lo0);
        u32 hi1 = split2(v.z, v.w, lo1);
        dh[k] = make_uint2(hi0, hi1);
        dl[k] = make_uint2(lo0, lo1);
    }
}

// ---------------- conv A -> bf16 hi/lo -----------------------------------------
__global__ void k_conv(const float* __restrict__ in, bf16* __restrict__ oh,
                       bf16* __restrict__ ol, int n8) {
    int t = blockIdx.x * 256 + threadIdx.x;
    if (t >= n8) return;
    float4 a = ((const float4*)in)[2 * t], b = ((const float4*)in)[2 * t + 1];
    u32 l0, l1, l2, l3;
    u32 h0 = split2(a.x, a.y, l0);
    u32 h1 = split2(a.z, a.w, l1);
    u32 h2 = split2(b.x, b.y, l2);
    u32 h3 = split2(b.z, b.w, l3);
    ((uint4*)oh)[t] = make_uint4(h0, h1, h2, h3);
    ((uint4*)ol)[t] = make_uint4(l0, l1, l2, l3);
}

// ---------------- bf16 hi/lo pair transpose ------------------------------------
__global__ void k_tbf(const bf16* __restrict__ ih, const bf16* __restrict__ il, int ldin,
                      bf16* __restrict__ oh, bf16* __restrict__ ol, int ldout) {
    __shared__ u32 th[64][33], tl[64][33];
    int k0 = blockIdx.x * 64, m0 = blockIdx.y * 64;
    int t = threadIdx.x;
#pragma unroll
    for (int j = 0; j < 8; j++) {
        int idx = t + j * 256;
        int kr = idx >> 5, mu = idx & 31;
        th[kr][mu] = *(const u32*)&ih[(size_t)(k0 + kr) * ldin + m0 + 2 * mu];
        tl[kr][mu] = *(const u32*)&il[(size_t)(k0 + kr) * ldin + m0 + 2 * mu];
    }
    __syncthreads();
#pragma unroll
    for (int j = 0; j < 8; j++) {
        int idx = t + j * 256;
        int mr = idx >> 5, ku = idx & 31;
        u32 u0 = th[2 * ku][mr >> 1], u1 = th[2 * ku + 1][mr >> 1];
        u32 v0 = tl[2 * ku][mr >> 1], v1 = tl[2 * ku + 1][mr >> 1];
        u32 sel = (mr & 1) ? 0x7632 : 0x5410;
        *(u32*)&oh[(size_t)(m0 + mr) * ldout + k0 + 2 * ku] = __byte_perm(u0, u1, sel);
        *(u32*)&ol[(size_t)(m0 + mr) * ldout + k0 + 2 * ku] = __byte_perm(v0, v1, sel);
    }
}

// ---------------- Bp left ------------------------------------------------------
__global__ void k_bpl(const float* __restrict__ R, const int* __restrict__ inact,
                      const float* __restrict__ dvec,
                      bf16* __restrict__ oh, bf16* __restrict__ ol) {
    __shared__ float tf[32][65];
    int k0 = blockIdx.x * 32, n0 = blockIdx.y * 64;
    int t = threadIdx.x;
#pragma unroll
    for (int j = 0; j < 8; j++) {
        int idx = t + j * 256;
        int kr = idx >> 6, nc = idx & 63;
        tf[kr][nc] = dvec[k0 + kr] * R[(size_t)inact[k0 + kr] * NN + n0 + nc];
    }
    __syncthreads();
#pragma unroll
    for (int j = 0; j < 4; j++) {
        int idx = t + j * 256;
        int nr = idx >> 4, ku = idx & 15;
        float v0 = tf[2 * ku][nr], v1 = tf[2 * ku + 1][nr];
        u32 lo, hi = split2(v0, v1, lo);
        *(u32*)&oh[(size_t)(n0 + nr) * NN + k0 + 2 * ku] = hi;
        *(u32*)&ol[(size_t)(n0 + nr) * NN + k0 + 2 * ku] = lo;
    }
}

// ---------------- maps / reductions / outputs ----------------------------------
__global__ void k_maps(const int* __restrict__ act, const int* __restrict__ inact,
                       int* winv, int* colmap) {
    int t = threadIdx.x;
    colmap[t] = -1;
    colmap[t + 1024] = -1;
    __syncthreads();
    winv[inact[t]] = t;
    winv[act[t]]   = DIMV + t;
    colmap[act[t]] = t;
}

__global__ void k_dred(const float* __restrict__ gpart, float* __restrict__ dvec) {
    int j = blockIdx.x * 256 + threadIdx.x;
    float s = 0.f;
#pragma unroll
    for (int b = 0; b < 16; b++) s += gpart[b * DIMV + j];
    dvec[j] = s;
}

__global__ void __launch_bounds__(256) k_dfill(const float* __restrict__ Daa,
                                               const int* __restrict__ colmap,
                                               const int* __restrict__ winv,
                                               const float* __restrict__ dvec,
                                               float* __restrict__ D,
                                               float* __restrict__ mc) {
    int gr = blockIdx.x, t = threadIdx.x;
    if (gr >= NN) {
        int j = gr - NN;
        float* row = mc + (size_t)j * DIMV;
        ((float4*)row)[t] = make_float4(0.f, 0.f, 0.f, 0.f);
        __syncthreads();
        if (t == 0) row[j] = dvec[j];
        return;
    }
    int a = colmap[gr];
    float* row = D + (size_t)gr * NN;
    if (a < 0) {
        float4 z = make_float4(0.f, 0.f, 0.f, 0.f);
#pragma unroll
        for (int j = 0; j < 2; j++) ((float4*)row)[t + j * 256] = z;
        __syncthreads();
        if (t == 0) row[gr] = dvec[winv[gr]];
    } else {
        const float* dr = Daa + (size_t)a * DIMV;
#pragma unroll
        for (int j = 0; j < 8; j++) {
            int cc = t + j * 256;
            int cm = colmap[cc];
            row[cc] = (cm >= 0) ? dr[cm] : 0.f;
        }
    }
}

// ---------------- launch --------------------------------------------------------
extern "C" void kernel_launch(void* const* d_in, const int* in_sizes, int n_in,
                              void* d_out, int out_size) {
    const float* A    = (const float*)d_in[0];
    const float* O    = (const float*)d_in[1];
    const int*   idx  = (const int*)d_in[2];
    const int*   act  = (const int*)d_in[3];
    const int*   inact= (const int*)d_in[4];
    float* out = (float*)d_out;

    float *R, *dv, *gpart, *Pk;
    int *winv, *colmap;
    bf16 *Ah, *Al, *Wh, *Wl, *T1ah, *T1al, *Dh, *Dl, *FTh, *FTl, *WTh, *WTl, *Bph, *Bpl;
    cudaGetSymbolAddress((void**)&R,     g_R);
    cudaGetSymbolAddress((void**)&dv,    g_d);
    cudaGetSymbolAddress((void**)&gpart, g_part);
    cudaGetSymbolAddress((void**)&Pk,    g_Pk);
    cudaGetSymbolAddress((void**)&winv,  g_winv);
    cudaGetSymbolAddress((void**)&colmap,g_colmap);
    cudaGetSymbolAddress((void**)&Ah,  g_Ah);   cudaGetSymbolAddress((void**)&Al,  g_Al);
    cudaGetSymbolAddress((void**)&Wh,  g_Wh);   cudaGetSymbolAddress((void**)&Wl,  g_Wl);
    cudaGetSymbolAddress((void**)&T1ah,g_T1ah); cudaGetSymbolAddress((void**)&T1al,g_T1al);
    cudaGetSymbolAddress((void**)&Dh,  g_Dh);   cudaGetSymbolAddress((void**)&Dl,  g_Dl);
    cudaGetSymbolAddress((void**)&FTh, g_FTh);  cudaGetSymbolAddress((void**)&FTl, g_FTl);
    cudaGetSymbolAddress((void**)&WTh, g_WTh);  cudaGetSymbolAddress((void**)&WTl, g_WTl);
    cudaGetSymbolAddress((void**)&Bph, g_Bph);  cudaGetSymbolAddress((void**)&Bpl, g_Bpl);

    const size_t NN2 = (size_t)NN * NN;
    float* o_arec  = out;
    float* o_right = out + NN2;
    float* o_D     = out + 2 * NN2;
    float* o_mc    = out + 3 * NN2;
    float* o_fc    = o_mc + (size_t)DIMV * DIMV;
    float* o_mw    = o_fc + (size_t)DIMV * DIMV;   // W fp32 = [Mi;Fa] contiguous

    const int smemR = 8 * NN * 2 * 4 + RWIN * 256 * 4 + RWIN * 16 * 4 + 8 * NN;

    // one-time setup (first call = correctness run, outside graph capture)
    static bool s_init = false;
    static cudaStream_t s2 = 0;
    static cudaEvent_t ePrep = 0, eDred = 0, eFcred = 0, eTb = 0, eBpl = 0, eDfill = 0;
    if (!s_init) {
        cudaFuncSetAttribute(k_right, cudaFuncAttributeMaxDynamicSharedMemorySize, smemR);
        cudaFuncSetAttribute(k_mma<14>, cudaFuncAttributeMaxDynamicSharedMemorySize, SMG);
        cudaFuncSetAttribute(k_mma<33>, cudaFuncAttributeMaxDynamicSharedMemorySize, SMG);
        cudaFuncSetAttribute(k_mma<2>,  cudaFuncAttributeMaxDynamicSharedMemorySize, SMG);
        cudaFuncSetAttribute(k_mma<17>, cudaFuncAttributeMaxDynamicSharedMemorySize, SMG);
        if (cudaStreamCreateWithFlags(&s2, cudaStreamNonBlocking) == cudaSuccess) {
            cudaEventCreateWithFlags(&ePrep,  cudaEventDisableTiming);
            cudaEventCreateWithFlags(&eDred,  cudaEventDisableTiming);
            cudaEventCreateWithFlags(&eFcred, cudaEventDisableTiming);
            cudaEventCreateWithFlags(&eTb,    cudaEventDisableTiming);
            cudaEventCreateWithFlags(&eBpl,   cudaEventDisableTiming);
            cudaEventCreateWithFlags(&eDfill, cudaEventDisableTiming);
        } else {
            s2 = 0;
        }
        s_init = true;
    }
    const bool ovl = (s2 != 0) && ePrep && eDred && eFcred && eTb && eBpl && eDfill;

    // ---- main-stream front end ----
    k_maps<<<1, 1024>>>(act, inact, winv, colmap);
    k_conv<<<(int)(NN2 / 8 / 256), 256>>>(A, Ah, Al, (int)(NN2 / 8));
    k_right<<<NN / KK, 256, smemR>>>(O, idx);
    k_prep<<<NN, 256>>>(R, winv, o_right, o_mw, Wh, Wl);

    if (ovl) cudaEventRecord(ePrep, 0);

    if (ovl) {
        // side stream: transposes overlap GEMM1
        cudaStreamWaitEvent(s2, ePrep, 0);
        k_tbf<<<dim3(NN / 64, NN / 64), 256, 0, s2>>>(Wh, Wl, NN, WTh, WTl, NN);   // WT
        k_tbf<<<dim3(DIMV / 64, NN / 64), 256, 0, s2>>>(Wh + (size_t)DIMV * NN,
                                                        Wl + (size_t)DIMV * NN,
                                                        NN, FTh, FTl, DIMV);       // FaT
        cudaEventRecord(eTb, s2);
    }

    // GEMM1: T1 = W @ A
    k_mma<14><<<dim3(16, 16), 256, SMG>>>(Wh, Wl, NN, Ah, Al, NN, NN,
                                          nullptr, 0, T1ah, T1al, NN, o_mw, gpart);
    k_dred<<<DIMV / 256, 256>>>(gpart, dv);
    if (ovl) cudaEventRecord(eDred, 0);

    if (ovl) {
        // side stream: Bp left overlaps GEMM2
        cudaStreamWaitEvent(s2, eDred, 0);
        k_bpl<<<dim3(DIMV / 32, NN / 64), 256, 0, s2>>>(R, inact, dv, Bph, Bpl);
        cudaEventRecord(eBpl, s2);
    }

    // GEMM2: D_aa split-K x2 + reduce
    k_mma<33><<<dim3(8, 16), 256, SMG>>>(T1ah, T1al, NN,
                                         Wh + (size_t)DIMV * NN, Wl + (size_t)DIMV * NN, NN,
                                         DIMV, Pk, DIMV, nullptr, nullptr, 0,
                                         nullptr, nullptr);
    k_fcred<<<DIMV, 256>>>(Pk, o_fc, Dh, Dl);
    if (ovl) cudaEventRecord(eFcred, 0);

    if (ovl) {
        // side stream: D + mc fill overlaps GEMM3/GEMM4
        cudaStreamWaitEvent(s2, eFcred, 0);
        k_dfill<<<NN + DIMV, 256, 0, s2>>>(o_fc, colmap, winv, dv, o_D, o_mc);
        cudaEventRecord(eDfill, s2);
    }

    if (!ovl) {
        k_tbf<<<dim3(DIMV / 64, NN / 64), 256>>>(Wh + (size_t)DIMV * NN,
                                                 Wl + (size_t)DIMV * NN, NN, FTh, FTl, DIMV);
    } else {
        cudaStreamWaitEvent(0, eTb, 0);      // need FaT (and WT later)
    }

    // GEMM3: P = FaT @ D_aa -> B' right half
    k_mma<2><<<dim3(8, 16), 256, SMG>>>(FTh, FTl, DIMV, Dh, Dl, DIMV, DIMV,
                                        nullptr, 0, Bph + DIMV, Bpl + DIMV, NN,
                                        nullptr, nullptr);

    if (!ovl) {
        k_bpl<<<dim3(DIMV / 32, NN / 64), 256>>>(R, inact, dv, Bph, Bpl);
        k_tbf<<<dim3(NN / 64, NN / 64), 256>>>(Wh, Wl, NN, WTh, WTl, NN);
    } else {
        cudaStreamWaitEvent(0, eBpl, 0);
    }

    // GEMM4: A_rec = WT @ B'^T (triangle + mirror)
    k_mma<17><<<136, 256, SMG>>>(WTh, WTl, NN, Bph, Bpl, NN, NN,
                                 o_arec, NN, nullptr, nullptr, 0,
                                 nullptr, nullptr);

    if (!ovl) {
        k_dfill<<<NN + DIMV, 256>>>(o_fc, colmap, winv, dv, o_D, o_mc);
    } else {
        cudaStreamWaitEvent(0, eDfill, 0);   // join side stream before return
    }
}